// round 4
// baseline (speedup 1.0000x reference)
#include <cuda_runtime.h>
#include <cstdint>
#include <math.h>

// ---------------- problem constants ----------------
#define BB   16
#define CC   256
#define MM   4096          // H*W
#define HID  256
#define NN   300
#define NCC  80

// output layout (flattened tuple: boxes, scores, cls, maps, div, sf)
#define OFF_BOXES  0LL
#define OFF_SCORES 19200LL
#define OFF_CLS    24000LL
#define OFF_MAPS   408000LL
#define OFF_DIV    20068800LL
#define OFF_SF     20068801LL

// pair-permutation of the contraction index m (applied to attn_t and vals)
#define PERM(m) (((m) & ~7) + 2 * ((m) & 3) + (((m) >> 2) & 1))

// ---------------- device scratch ----------------
__device__ float g_feats[BB * 128 * MM];
__device__ float g_keys [BB * 64 * MM];
__device__ float g_vals [BB * 256 * MM];            // tf32-rounded, m-permuted
__device__ float g_pos  [128 * MM];
__device__ float g_posk [64 * MM];
__device__ float g_posv [256 * MM];
__device__ float g_logits[(long long)BB * 4 * NN * MM];
__device__ float g_attn_t[(long long)BB * NN * MM]; // tf32-rounded, m-permuted attn
__device__ float g_invn [BB * NN];
__device__ float g_sf   [BB * NN * HID];
__device__ float g_h1   [BB * NN * 256];
__device__ float g_h2   [BB * NN * 128];
__device__ float g_bns  [128];
__device__ float g_bnt  [128];
__device__ float g_divpart[256];

__device__ __forceinline__ float tf32_rna(float v) {
    uint32_t u;
    asm("cvt.rna.tf32.f32 %0, %1;" : "=r"(u) : "f"(v));
    return __uint_as_float(u);
}
__device__ __forceinline__ uint32_t smem_u32(const void* p) {
    uint32_t a;
    asm("{ .reg .u64 t; cvta.to.shared.u64 t, %1; cvt.u32.u64 %0, t; }" : "=r"(a) : "l"(p));
    return a;
}
__device__ __forceinline__ void mma_tf32(float c[4], const uint32_t a[4], const uint32_t b[2]) {
    asm volatile(
        "mma.sync.aligned.m16n8k8.row.col.f32.tf32.tf32.f32 "
        "{%0,%1,%2,%3}, {%4,%5,%6,%7}, {%8,%9}, {%0,%1,%2,%3};"
        : "+f"(c[0]), "+f"(c[1]), "+f"(c[2]), "+f"(c[3])
        : "r"(a[0]), "r"(a[1]), "r"(a[2]), "r"(a[3]), "r"(b[0]), "r"(b[1]));
}
template<int N> __device__ __forceinline__ void cp_wait() {
    asm volatile("cp.async.wait_group %0;" :: "n"(N) : "memory");
}
__device__ __forceinline__ void cp_commit() {
    asm volatile("cp.async.commit_group;" ::: "memory");
}
__device__ __forceinline__ void cp16(uint32_t dst, const float* src) {
    asm volatile("cp.async.cg.shared.global [%0], [%1], 16;" :: "r"(dst), "l"(src) : "memory");
}

// ---------------- small kernels ----------------
__global__ void init_kernel(const float* __restrict__ fp_b, const float* __restrict__ bn_g,
                            const float* __restrict__ bn_b, const float* __restrict__ bn_m,
                            const float* __restrict__ bn_v) {
    int t = threadIdx.x;
    if (t < 128) {
        float s = bn_g[t] * rsqrtf(bn_v[t] + 1e-5f);
        g_bns[t] = s;
        g_bnt[t] = (fp_b[t] - bn_m[t]) * s + bn_b[t];
    }
}

__global__ void pos_kernel(const float* __restrict__ pos_w, const float* __restrict__ pos_b) {
    int m = blockIdx.x * 256 + threadIdx.x;
    int o = blockIdx.y;
    int hh = m >> 6, ww = m & 63;
    float y = -1.0f + 2.0f * (float)hh / 63.0f;
    float x = -1.0f + 2.0f * (float)ww / 63.0f;
    g_pos[(long long)o * MM + m] = pos_w[o * 2] * y + pos_w[o * 2 + 1] * x + pos_b[o];
}

// ---------------- SIMT GEMM NN ----------------
// EPI 0: alpha*acc+bias  EPI 1: relu(acc*v1+v2)  EPI 2: acc+C0  EPI 3: tf32(acc+C0), m-permuted store
#define TILE 128
#define BK   16

template<int EPI, int ZMAP>
__global__ void __launch_bounds__(256) gemm_nn(
    const float* __restrict__ Wb, int ldw,
    const float* __restrict__ Xb, float* __restrict__ Cb,
    int O, int M, int K,
    long long wz, long long xz, long long cz,
    const float* __restrict__ v1, const float* __restrict__ v2,
    float alpha, const float* __restrict__ C0)
{
    __shared__ float Ws[BK][TILE + 4];
    __shared__ float Xs[BK][TILE + 4];
    int z = blockIdx.z;
    const float* W; const float* X; float* C;
    if (ZMAP == 0) { W = Wb + wz * z; X = Xb + xz * z; C = Cb + cz * z; }
    else {
        int b = z >> 2, h = z & 3;
        W = Wb + h * 16;
        X = Xb + ((long long)(b * 64 + h * 16)) * M;
        C = Cb + (long long)z * O * M;
    }
    int t = threadIdx.x, tx = t & 15, ty = t >> 4;
    int oB = blockIdx.y * TILE, mB = blockIdx.x * TILE;

    float acc[8][8];
#pragma unroll
    for (int i = 0; i < 8; i++)
#pragma unroll
        for (int j = 0; j < 8; j++) acc[i][j] = 0.f;

    for (int k0 = 0; k0 < K; k0 += BK) {
#pragma unroll
        for (int r = 0; r < 2; r++) {
            int idx = t + r * 256;
            int row = idx >> 2, kq = (idx & 3) * 4;
            float4 v = make_float4(0.f, 0.f, 0.f, 0.f);
            int o = oB + row;
            if (o < O) v = *(const float4*)(W + (long long)o * ldw + k0 + kq);
            Ws[kq + 0][row] = v.x; Ws[kq + 1][row] = v.y;
            Ws[kq + 2][row] = v.z; Ws[kq + 3][row] = v.w;
        }
#pragma unroll
        for (int r = 0; r < 2; r++) {
            int idx = t + r * 256;
            int row = idx >> 5, cq = (idx & 31) * 4;
            float4 v = *(const float4*)(X + (long long)(k0 + row) * M + mB + cq);
            *(float4*)&Xs[row][cq] = v;
        }
        __syncthreads();
#pragma unroll
        for (int k = 0; k < BK; k++) {
            float a[8], bv[8];
            *(float4*)&a[0]  = *(const float4*)&Ws[k][ty * 4];
            *(float4*)&a[4]  = *(const float4*)&Ws[k][ty * 4 + 64];
            *(float4*)&bv[0] = *(const float4*)&Xs[k][tx * 4];
            *(float4*)&bv[4] = *(const float4*)&Xs[k][tx * 4 + 64];
#pragma unroll
            for (int i = 0; i < 8; i++)
#pragma unroll
                for (int j = 0; j < 8; j++) acc[i][j] += a[i] * bv[j];
        }
        __syncthreads();
    }
#pragma unroll
    for (int i = 0; i < 8; i++) {
        int o = oB + (i < 4 ? ty * 4 + i : 64 + ty * 4 + i - 4);
        if (o >= O) continue;
        float e1 = 0.f, e2 = 0.f, bo = 0.f;
        if (EPI == 1) { e1 = v1[o]; e2 = v2[o]; }
        if (EPI == 0 && v1) bo = v1[o];
#pragma unroll
        for (int j = 0; j < 8; j++) {
            int m = mB + (j < 4 ? tx * 4 + j : 64 + tx * 4 + j - 4);
            if (m >= M) continue;
            float v = acc[i][j];
            long long ci = m;
            if (EPI == 0)      v = alpha * v + bo;
            else if (EPI == 1) v = fmaxf(v * e1 + e2, 0.f);
            else if (EPI == 2) v = v + C0[(long long)o * M + m];
            else             { v = tf32_rna(v + C0[(long long)o * M + m]); ci = PERM(m); }
            C[(long long)o * M + ci] = v;
        }
    }
}

// ---------------- SIMT GEMM NT (heads) ----------------
template<int EPI>
__global__ void __launch_bounds__(256) gemm_nt(
    const float* __restrict__ Ab, const float* __restrict__ Bb, float* __restrict__ Cb,
    int I, int J, int K, const float* __restrict__ bias)
{
    __shared__ float As[BK][TILE + 4];
    __shared__ float Bs[BK][TILE + 4];
    int t = threadIdx.x, tx = t & 15, ty = t >> 4;
    int iB = blockIdx.y * TILE, jB = blockIdx.x * TILE;

    float acc[8][8];
#pragma unroll
    for (int i = 0; i < 8; i++)
#pragma unroll
        for (int j = 0; j < 8; j++) acc[i][j] = 0.f;

    for (int k0 = 0; k0 < K; k0 += BK) {
#pragma unroll
        for (int r = 0; r < 2; r++) {
            int idx = t + r * 256;
            int row = idx >> 2, kq = (idx & 3) * 4;
            float4 v = make_float4(0.f, 0.f, 0.f, 0.f);
            int i = iB + row;
            if (i < I) v = *(const float4*)(Ab + (long long)i * K + k0 + kq);
            As[kq + 0][row] = v.x; As[kq + 1][row] = v.y;
            As[kq + 2][row] = v.z; As[kq + 3][row] = v.w;
        }
#pragma unroll
        for (int r = 0; r < 2; r++) {
            int idx = t + r * 256;
            int row = idx >> 2, kq = (idx & 3) * 4;
            float4 v = make_float4(0.f, 0.f, 0.f, 0.f);
            int j = jB + row;
            if (j < J) v = *(const float4*)(Bb + (long long)j * K + k0 + kq);
            Bs[kq + 0][row] = v.x; Bs[kq + 1][row] = v.y;
            Bs[kq + 2][row] = v.z; Bs[kq + 3][row] = v.w;
        }
        __syncthreads();
#pragma unroll
        for (int k = 0; k < BK; k++) {
            float a[8], bv[8];
            *(float4*)&a[0]  = *(const float4*)&As[k][ty * 4];
            *(float4*)&a[4]  = *(const float4*)&As[k][ty * 4 + 64];
            *(float4*)&bv[0] = *(const float4*)&Bs[k][tx * 4];
            *(float4*)&bv[4] = *(const float4*)&Bs[k][tx * 4 + 64];
#pragma unroll
            for (int i = 0; i < 8; i++)
#pragma unroll
                for (int j = 0; j < 8; j++) acc[i][j] += a[i] * bv[j];
        }
        __syncthreads();
    }
#pragma unroll
    for (int i = 0; i < 8; i++) {
        int ii = iB + (i < 4 ? ty * 4 + i : 64 + ty * 4 + i - 4);
        if (ii >= I) continue;
#pragma unroll
        for (int j = 0; j < 8; j++) {
            int jj = jB + (j < 4 ? tx * 4 + j : 64 + tx * 4 + j - 4);
            if (jj >= J) continue;
            float v = acc[i][j];
            if (bias) v += bias[jj];
            if (EPI == 1) v = fmaxf(v, 0.f);
            else if (EPI == 2) v = 1.0f / (1.0f + __expf(-v));
            Cb[(long long)ii * J + jj] = v;
        }
    }
}

// ---------------- softmax; writes exact maps + tf32 m-permuted attn_t ----------------
__global__ void softmax_kernel(const float* __restrict__ logits,
                               float* __restrict__ attn, float* __restrict__ attn_t,
                               float* __restrict__ invn)
{
    extern __shared__ float sm[];
    __shared__ float red[256];
    int bn = blockIdx.x;
    int b = bn / NN, n = bn - b * NN;
    int t = threadIdx.x;
#pragma unroll
    for (int h = 0; h < 4; h++) {
        const float* src = logits + ((long long)(b * 4 + h) * NN + n) * MM;
        for (int m = t; m < MM; m += 256) sm[h * MM + m] = src[m];
    }
    __syncthreads();
    float mx[4], rs[4];
#pragma unroll
    for (int h = 0; h < 4; h++) {
        float lm = -1e30f;
        for (int m = t; m < MM; m += 256) lm = fmaxf(lm, sm[h * MM + m]);
        red[t] = lm; __syncthreads();
        for (int k = 128; k > 0; k >>= 1) { if (t < k) red[t] = fmaxf(red[t], red[t + k]); __syncthreads(); }
        mx[h] = red[0]; __syncthreads();
        float ls = 0.f;
        for (int m = t; m < MM; m += 256) ls += __expf(sm[h * MM + m] - mx[h]);
        red[t] = ls; __syncthreads();
        for (int k = 128; k > 0; k >>= 1) { if (t < k) red[t] += red[t + k]; __syncthreads(); }
        rs[h] = 0.25f / red[0]; __syncthreads();
    }
    float ss = 0.f;
    float* dst  = attn + (long long)bn * MM;
    float* dstt = attn_t + (long long)bn * MM;
    for (int m = t; m < MM; m += 256) {
        float a = __expf(sm[m] - mx[0]) * rs[0]
                + __expf(sm[MM + m] - mx[1]) * rs[1]
                + __expf(sm[2 * MM + m] - mx[2]) * rs[2]
                + __expf(sm[3 * MM + m] - mx[3]) * rs[3];
        dst[m] = a; dstt[PERM(m)] = tf32_rna(a); ss += a * a;
    }
    red[t] = ss; __syncthreads();
    for (int k = 128; k > 0; k >>= 1) { if (t < k) red[t] += red[t + k]; __syncthreads(); }
    if (t == 0) { float nr = sqrtf(red[0]); invn[bn] = 1.0f / fmaxf(nr, 1e-12f); }
}

// ---------------- diversity ----------------
__global__ void div_s_kernel(const float* __restrict__ attn, const float* __restrict__ invn)
{
    __shared__ float sinv[304];
    __shared__ float red[256];
    int b = blockIdx.y, t = threadIdx.x;
    for (int i = t; i < NN; i += 256) sinv[i] = invn[b * NN + i];
    __syncthreads();
    int m = blockIdx.x * 256 + t;
    const float* base = attn + (long long)b * NN * MM + m;
    float s = 0.f;
    for (int n = 0; n < NN; n++) s += base[(long long)n * MM] * sinv[n];
    red[t] = s * s; __syncthreads();
    for (int k = 128; k > 0; k >>= 1) { if (t < k) red[t] += red[t + k]; __syncthreads(); }
    if (t == 0) g_divpart[b * 16 + blockIdx.x] = red[0];
}

__global__ void finalize_div(float* __restrict__ outdiv)
{
    __shared__ float red[256];
    int t = threadIdx.x;
    red[t] = g_divpart[t]; __syncthreads();
    for (int k = 128; k > 0; k >>= 1) { if (t < k) red[t] += red[t + k]; __syncthreads(); }
    if (t == 0) outdiv[0] = (red[0] - (float)(BB * NN)) * (0.1f / ((float)NN * (NN - 1)));
}

// ---------------- LayerNorm(256) + ReLU, in place ----------------
__global__ void ln_relu_kernel(float* __restrict__ z, const float* __restrict__ g,
                               const float* __restrict__ bb)
{
    __shared__ float red[256];
    __shared__ float mu_s, var_s;
    int row = blockIdx.x, t = threadIdx.x;
    float v = z[(long long)row * 256 + t];
    red[t] = v; __syncthreads();
    for (int k = 128; k > 0; k >>= 1) { if (t < k) red[t] += red[t + k]; __syncthreads(); }
    if (t == 0) mu_s = red[0] * (1.0f / 256.0f);
    __syncthreads();
    float d = v - mu_s;
    red[t] = d * d; __syncthreads();
    for (int k = 128; k > 0; k >>= 1) { if (t < k) red[t] += red[t + k]; __syncthreads(); }
    if (t == 0) var_s = red[0] * (1.0f / 256.0f);
    __syncthreads();
    float o = d * rsqrtf(var_s + 1e-5f) * g[t] + bb[t];
    z[(long long)row * 256 + t] = fmaxf(o, 0.f);
}

// ================= mma.sync tf32 GEMM with cp.async pipeline: sf = attn @ vals^T =================
// Block 256 thr (8 warps, 4n x 2c), tile 128n x 128c. K in 128 chunks of 32, 4-stage cp.async.
// smem stage: A 128x32 + B 128x32 floats, 16B-granule XOR swizzle. 4 stages = 128 KB.
#define SF_STAGES 4
#define SF_STAGEF 8192                         // floats per stage (A 4096 + B 4096)
#define SF_SMEM   (SF_STAGES * SF_STAGEF * 4)  // 131072 bytes

__device__ __forceinline__ void sf_copy(float* stage, const float* Ab, const float* Bb,
                                        int n0, int c0, int ch, int t)
{
    uint32_t sa = smem_u32(stage);
#pragma unroll
    for (int i = 0; i < 4; i++) {
        int gi = t + i * 256;
        int row = gi >> 3, gc = gi & 7;
        int ar = n0 + row; ar = ar < NN ? ar : NN - 1;
        const float* src = Ab + (long long)ar * MM + ch * 32 + gc * 4;
        uint32_t dst = sa + (uint32_t)(row * 32 + ((gc ^ (row & 7)) << 2)) * 4u;
        cp16(dst, src);
    }
#pragma unroll
    for (int i = 0; i < 4; i++) {
        int gi = t + i * 256;
        int row = gi >> 3, gc = gi & 7;
        const float* src = Bb + (long long)(c0 + row) * MM + ch * 32 + gc * 4;
        uint32_t dst = sa + (uint32_t)(4096 + row * 32 + ((gc ^ (row & 7)) << 2)) * 4u;
        cp16(dst, src);
    }
}

__global__ void __launch_bounds__(256, 1) sf_hmma_kernel(
    const float* __restrict__ attn_t, const float* __restrict__ vals,
    float* __restrict__ sfb, float* __restrict__ outsf)
{
    extern __shared__ float smf[];
    int t = threadIdx.x;
    int lane = t & 31, w = t >> 5;
    int wn0 = (w & 3) * 32, wc0 = (w >> 2) * 64;
    int g = lane >> 2, tq = lane & 3;
    int n0 = blockIdx.y * 128, c0 = blockIdx.x * 128, b = blockIdx.z;

    const float* Ab = attn_t + (long long)b * NN * MM;
    const float* Bb = vals + (long long)b * HID * MM;

    float acc[2][8][4];
#pragma unroll
    for (int mi = 0; mi < 2; mi++)
#pragma unroll
        for (int ni = 0; ni < 8; ni++)
#pragma unroll
            for (int r = 0; r < 4; r++) acc[mi][ni][r] = 0.f;

    // prologue: stages 0..2
#pragma unroll
    for (int s = 0; s < SF_STAGES - 1; s++) {
        sf_copy(smf + s * SF_STAGEF, Ab, Bb, n0, c0, s, t);
        cp_commit();
    }

    for (int ch = 0; ch < MM / 32; ch++) {
        cp_wait<2>();
        __syncthreads();
        int nxt = ch + SF_STAGES - 1;
        if (nxt < MM / 32)
            sf_copy(smf + (nxt & 3) * SF_STAGEF, Ab, Bb, n0, c0, nxt, t);
        cp_commit();

        const float* As  = smf + (ch & 3) * SF_STAGEF;
        const float* Bs2 = As + 4096;
#pragma unroll
        for (int ks = 0; ks < 4; ks++) {
            int woff = (((ks * 2 + (tq >> 1)) ^ g) << 2) + (tq & 1) * 2;
            uint32_t a[2][4];
#pragma unroll
            for (int mi = 0; mi < 2; mi++) {
                int r = wn0 + 16 * mi + g;
                float2 u = *(const float2*)(As + r * 32 + woff);
                float2 v = *(const float2*)(As + (r + 8) * 32 + woff);
                a[mi][0] = __float_as_uint(u.x); a[mi][2] = __float_as_uint(u.y);
                a[mi][1] = __float_as_uint(v.x); a[mi][3] = __float_as_uint(v.y);
            }
            uint32_t bf[8][2];
#pragma unroll
            for (int ni = 0; ni < 8; ni++) {
                int c = wc0 + ni * 8 + g;
                float2 bv = *(const float2*)(Bs2 + c * 32 + woff);
                bf[ni][0] = __float_as_uint(bv.x); bf[ni][1] = __float_as_uint(bv.y);
            }
#pragma unroll
            for (int mi = 0; mi < 2; mi++)
#pragma unroll
                for (int ni = 0; ni < 8; ni++)
                    mma_tf32(acc[mi][ni], a[mi], bf[ni]);
        }
        __syncthreads();
    }

    // epilogue
#pragma unroll
    for (int mi = 0; mi < 2; mi++) {
#pragma unroll
        for (int ni = 0; ni < 8; ni++) {
            int c = c0 + wc0 + ni * 8 + 2 * tq;
            int n1 = n0 + wn0 + 16 * mi + g;
            if (n1 < NN) {
                long long o = ((long long)b * NN + n1) * HID + c;
                float2 v = make_float2(acc[mi][ni][0], acc[mi][ni][1]);
                *(float2*)(sfb + o) = v;
                outsf[o] = v.x; outsf[o + 1] = v.y;
            }
            int n2 = n1 + 8;
            if (n2 < NN) {
                long long o = ((long long)b * NN + n2) * HID + c;
                float2 v = make_float2(acc[mi][ni][2], acc[mi][ni][3]);
                *(float2*)(sfb + o) = v;
                outsf[o] = v.x; outsf[o + 1] = v.y;
            }
        }
    }
}

// ---------------- host ----------------
extern "C" void kernel_launch(void* const* d_in, const int* in_sizes, int n_in,
                              void* d_out_, int out_size)
{
    const float* x      = (const float*)d_in[0];
    const float* q      = (const float*)d_in[1];
    const float* pos_w  = (const float*)d_in[2];
    const float* pos_b  = (const float*)d_in[3];
    const float* fp_w   = (const float*)d_in[4];
    const float* fp_b   = (const float*)d_in[5];
    const float* bn_g   = (const float*)d_in[6];
    const float* bn_b   = (const float*)d_in[7];
    const float* bn_m   = (const float*)d_in[8];
    const float* bn_v   = (const float*)d_in[9];
    const float* key_w  = (const float*)d_in[10];
    const float* key_b  = (const float*)d_in[11];
    const float* val_w  = (const float*)d_in[12];
    const float* val_b  = (const float*)d_in[13];
    const float* ctp_w  = (const float*)d_in[14];
    const float* ctp_b  = (const float*)d_in[15];
    const float* bb1_w  = (const float*)d_in[16];
    const float* bb1_b  = (const float*)d_in[17];
    const float* bbln_g = (const float*)d_in[18];
    const float* bbln_b = (const float*)d_in[19];
    const float* bb2_w  = (const float*)d_in[20];
    const float* bb2_b  = (const float*)d_in[21];
    const float* bb3_w  = (const float*)d_in[22];
    const float* bb3_b  = (const float*)d_in[23];
    const float* ch1_w  = (const float*)d_in[24];
    const float* ch1_b  = (const float*)d_in[25];
    const float* chln_g = (const float*)d_in[26];
    const float* chln_b = (const float*)d_in[27];
    const float* ch2_w  = (const float*)d_in[28];
    const float* ch2_b  = (const float*)d_in[29];
    const float* ch3_w  = (const float*)d_in[30];
    const float* ch3_b  = (const float*)d_in[31];
    float* out = (float*)d_out_;

    float *feats, *keys, *vals, *pos, *posk, *posv, *logits, *attn_t, *invn, *sfb, *h1, *h2, *bns, *bnt;
    cudaGetSymbolAddress((void**)&feats,  g_feats);
    cudaGetSymbolAddress((void**)&keys,   g_keys);
    cudaGetSymbolAddress((void**)&vals,   g_vals);
    cudaGetSymbolAddress((void**)&pos,    g_pos);
    cudaGetSymbolAddress((void**)&posk,   g_posk);
    cudaGetSymbolAddress((void**)&posv,   g_posv);
    cudaGetSymbolAddress((void**)&logits, g_logits);
    cudaGetSymbolAddress((void**)&attn_t, g_attn_t);
    cudaGetSymbolAddress((void**)&invn,   g_invn);
    cudaGetSymbolAddress((void**)&sfb,    g_sf);
    cudaGetSymbolAddress((void**)&h1,     g_h1);
    cudaGetSymbolAddress((void**)&h2,     g_h2);
    cudaGetSymbolAddress((void**)&bns,    g_bns);
    cudaGetSymbolAddress((void**)&bnt,    g_bnt);

    cudaFuncSetAttribute(softmax_kernel, cudaFuncAttributeMaxDynamicSharedMemorySize, 4 * MM * 4);
    cudaFuncSetAttribute(sf_hmma_kernel, cudaFuncAttributeMaxDynamicSharedMemorySize, SF_SMEM);

    // 1. BN fold
    init_kernel<<<1, 128>>>(fp_b, bn_g, bn_b, bn_m, bn_v);
    // 2. positional channels
    pos_kernel<<<dim3(16, 128), 256>>>(pos_w, pos_b);
    // 3. batch-invariant pos contributions (include biases)
    gemm_nn<0, 0><<<dim3(32, 1, 1), 256>>>(key_w + 128, 256, pos, posk, 64, MM, 128,
                                           0, 0, 0, key_b, nullptr, 1.f, nullptr);
    gemm_nn<0, 0><<<dim3(32, 2, 1), 256>>>(val_w + 128, 256, pos, posv, 256, MM, 128,
                                           0, 0, 0, val_b, nullptr, 1.f, nullptr);
    // 4. feats = relu(bn(fp_w[:128] @ x))
    gemm_nn<1, 0><<<dim3(32, 1, BB), 256>>>(fp_w, 256, x, feats, 128, MM, 256,
                                            0, (long long)CC * MM, 128LL * MM, bns, bnt, 1.f, nullptr);
    // 5. keys (exact) / vals (tf32-rounded, m-permuted for the HMMA consumer)
    gemm_nn<2, 0><<<dim3(32, 1, BB), 256>>>(key_w, 256, feats, keys, 64, MM, 128,
                                            0, 128LL * MM, 64LL * MM, nullptr, nullptr, 1.f, posk);
    gemm_nn<3, 0><<<dim3(32, 2, BB), 256>>>(val_w, 256, feats, vals, 256, MM, 128,
                                            0, 128LL * MM, 256LL * MM, nullptr, nullptr, 1.f, posv);
    // 6. logits
    gemm_nn<0, 1><<<dim3(32, 3, BB * 4), 256>>>(q, 64, keys, logits, NN, MM, 16,
                                                0, 0, 0, nullptr, nullptr, 0.25f, nullptr);
    // 7. softmax: exact maps -> d_out, tf32 m-permuted attn_t -> scratch
    softmax_kernel<<<BB * NN, 256, 4 * MM * 4>>>(logits, out + OFF_MAPS, attn_t, invn);
    // 8. diversity
    div_s_kernel<<<dim3(16, BB), 256>>>(out + OFF_MAPS, invn);
    finalize_div<<<1, 256>>>(out + OFF_DIV);
    // 9. sf = attn @ vals^T — mma.sync tf32 + cp.async 4-stage pipeline
    sf_hmma_kernel<<<dim3(2, 3, BB), 256, SF_SMEM>>>(attn_t, vals, sfb, out + OFF_SF);
    // 10. box head
    gemm_nt<0><<<dim3(2, 38, 1), 256>>>(sfb, bb1_w, h1, BB * NN, 256, 256, bb1_b);
    ln_relu_kernel<<<BB * NN, 256>>>(h1, bbln_g, bbln_b);
    gemm_nt<1><<<dim3(1, 38, 1), 256>>>(h1, bb2_w, h2, BB * NN, 128, 256, bb2_b);
    gemm_nt<0><<<dim3(1, 38, 1), 256>>>(h2, bb3_w, out + OFF_BOXES, BB * NN, 4, 128, bb3_b);
    // 11. score head
    gemm_nt<0><<<dim3(2, 38, 1), 256>>>(sfb, ch1_w, h1, BB * NN, 256, 256, ch1_b);
    ln_relu_kernel<<<BB * NN, 256>>>(h1, chln_g, chln_b);
    gemm_nt<1><<<dim3(1, 38, 1), 256>>>(h1, ch2_w, h2, BB * NN, 128, 256, ch2_b);
    gemm_nt<2><<<dim3(1, 38, 1), 256>>>(h2, ch3_w, out + OFF_SCORES, BB * NN, 1, 128, ch3_b);
    // 12. class head
    gemm_nt<0><<<dim3(1, 38, 1), 256>>>(sfb, ctp_w, out + OFF_CLS, BB * NN, NCC, 256, ctp_b);
}

// round 6
// speedup vs baseline: 1.2657x; 1.2657x over previous
#include <cuda_runtime.h>
#include <cstdint>
#include <math.h>

// ---------------- problem constants ----------------
#define BB   16
#define CC   256
#define MM   4096          // H*W
#define HID  256
#define NN   300
#define NCC  80

// output layout (flattened tuple: boxes, scores, cls, maps, div, sf)
#define OFF_BOXES  0LL
#define OFF_SCORES 19200LL
#define OFF_CLS    24000LL
#define OFF_MAPS   408000LL
#define OFF_DIV    20068800LL
#define OFF_SF     20068801LL

// ---------------- device scratch ----------------
__device__ float g_ft   [BB * 128 * MM];            // feats transposed [b][m][128], tf32
__device__ float g_kt   [BB * 64 * MM];             // keys transposed [b][m][64], tf32
__device__ float g_vals [BB * 256 * MM];            // vals [b][c][m], tf32
__device__ float g_pos  [128 * MM];
__device__ float g_posk [64 * MM];                  // pos part of keys [o][m] (fp32)
__device__ float g_poskt[MM * 64];                  // transposed [m][o]
__device__ float g_posv [256 * MM];                 // pos part of vals [c][m] (fp32)
__device__ float g_logits[(long long)BB * 4 * NN * MM]; // also aliases xt (first 16.8M floats)
__device__ float g_attn_t[(long long)BB * NN * MM]; // tf32-rounded attn
__device__ float g_invn [BB * NN];
__device__ float g_sf   [BB * NN * HID];
__device__ float g_h1   [BB * NN * 256];
__device__ float g_h2   [BB * NN * 128];
__device__ float g_bns  [128];
__device__ float g_bnt  [128];
__device__ float g_divpart[256];
__device__ float g_fpwt [128 * 256];                // tf32 weight copies
__device__ float g_keywt[64 * 256];
__device__ float g_valwt[256 * 256];
__device__ float g_qt   [NN * 64];                  // q * 0.25, tf32

__device__ __forceinline__ float tf32_rna(float v) {
    uint32_t u;
    asm("cvt.rna.tf32.f32 %0, %1;" : "=r"(u) : "f"(v));
    return __uint_as_float(u);
}
__device__ __forceinline__ void mma_tf32(float c[4], const uint32_t a[4], const uint32_t b[2]) {
    asm volatile(
        "mma.sync.aligned.m16n8k8.row.col.f32.tf32.tf32.f32 "
        "{%0,%1,%2,%3}, {%4,%5,%6,%7}, {%8,%9}, {%0,%1,%2,%3};"
        : "+f"(c[0]), "+f"(c[1]), "+f"(c[2]), "+f"(c[3])
        : "r"(a[0]), "r"(a[1]), "r"(a[2]), "r"(a[3]), "r"(b[0]), "r"(b[1]));
}

// ---------------- small kernels ----------------
__global__ void init_kernel(const float* __restrict__ fp_b, const float* __restrict__ bn_g,
                            const float* __restrict__ bn_b, const float* __restrict__ bn_m,
                            const float* __restrict__ bn_v) {
    int t = threadIdx.x;
    if (t < 128) {
        float s = bn_g[t] * rsqrtf(bn_v[t] + 1e-5f);
        g_bns[t] = s;
        g_bnt[t] = (fp_b[t] - bn_m[t]) * s + bn_b[t];
    }
}

__global__ void round_kernel(const float* __restrict__ src, float* __restrict__ dst,
                             int n, float scale) {
    int i = blockIdx.x * 256 + threadIdx.x;
    if (i < n) dst[i] = tf32_rna(src[i] * scale);
}

__global__ void pos_kernel(const float* __restrict__ pos_w, const float* __restrict__ pos_b) {
    int m = blockIdx.x * 256 + threadIdx.x;
    int o = blockIdx.y;
    int hh = m >> 6, ww = m & 63;
    float y = -1.0f + 2.0f * (float)hh / 63.0f;
    float x = -1.0f + 2.0f * (float)ww / 63.0f;
    g_pos[(long long)o * MM + m] = pos_w[o * 2] * y + pos_w[o * 2 + 1] * x + pos_b[o];
}

// 32x32 tiled transpose: dst[c][r] = (round?) src[r][c]; rows, cols multiples of 32
template<bool RND>
__global__ void transpose_kernel(const float* __restrict__ src, float* __restrict__ dst,
                                 int rows, int cols, long long zsrc, long long zdst)
{
    __shared__ float tile[32][33];
    int b = blockIdx.z;
    const float* s = src + zsrc * b;
    float* d = dst + zdst * b;
    int c0 = blockIdx.x * 32, r0 = blockIdx.y * 32;
    int tx = threadIdx.x, ty = threadIdx.y;    // (32, 8)
#pragma unroll
    for (int k = 0; k < 4; k++)
        tile[ty + 8 * k][tx] = s[(long long)(r0 + ty + 8 * k) * cols + c0 + tx];
    __syncthreads();
#pragma unroll
    for (int k = 0; k < 4; k++) {
        float v = tile[tx][ty + 8 * k];
        if (RND) v = tf32_rna(v);
        d[(long long)(c0 + ty + 8 * k) * rows + r0 + tx] = v;
    }
}

// ---------------- SIMT GEMM NN (only for pos contributions) ----------------
#define TILE 128
#define BK   16

__global__ void __launch_bounds__(256) gemm_nn_pos(
    const float* __restrict__ W, int ldw,
    const float* __restrict__ X, float* __restrict__ C,
    int O, int M, int K, const float* __restrict__ bias)
{
    __shared__ float Ws[BK][TILE + 4];
    __shared__ float Xs[BK][TILE + 4];
    int t = threadIdx.x, tx = t & 15, ty = t >> 4;
    int oB = blockIdx.y * TILE, mB = blockIdx.x * TILE;

    float acc[8][8];
#pragma unroll
    for (int i = 0; i < 8; i++)
#pragma unroll
        for (int j = 0; j < 8; j++) acc[i][j] = 0.f;

    for (int k0 = 0; k0 < K; k0 += BK) {
#pragma unroll
        for (int r = 0; r < 2; r++) {
            int idx = t + r * 256;
            int row = idx >> 2, kq = (idx & 3) * 4;
            float4 v = make_float4(0.f, 0.f, 0.f, 0.f);
            int o = oB + row;
            if (o < O) v = *(const float4*)(W + (long long)o * ldw + k0 + kq);
            Ws[kq + 0][row] = v.x; Ws[kq + 1][row] = v.y;
            Ws[kq + 2][row] = v.z; Ws[kq + 3][row] = v.w;
        }
#pragma unroll
        for (int r = 0; r < 2; r++) {
            int idx = t + r * 256;
            int row = idx >> 5, cq = (idx & 31) * 4;
            float4 v = *(const float4*)(X + (long long)(k0 + row) * M + mB + cq);
            *(float4*)&Xs[row][cq] = v;
        }
        __syncthreads();
#pragma unroll
        for (int k = 0; k < BK; k++) {
            float a[8], bv[8];
            *(float4*)&a[0]  = *(const float4*)&Ws[k][ty * 4];
            *(float4*)&a[4]  = *(const float4*)&Ws[k][ty * 4 + 64];
            *(float4*)&bv[0] = *(const float4*)&Xs[k][tx * 4];
            *(float4*)&bv[4] = *(const float4*)&Xs[k][tx * 4 + 64];
#pragma unroll
            for (int i = 0; i < 8; i++)
#pragma unroll
                for (int j = 0; j < 8; j++) acc[i][j] += a[i] * bv[j];
        }
        __syncthreads();
    }
#pragma unroll
    for (int i = 0; i < 8; i++) {
        int o = oB + (i < 4 ? ty * 4 + i : 64 + ty * 4 + i - 4);
        if (o >= O) continue;
        float bo = bias[o];
#pragma unroll
        for (int j = 0; j < 8; j++) {
            int m = mB + (j < 4 ? tx * 4 + j : 64 + tx * 4 + j - 4);
            C[(long long)o * M + m] = acc[i][j] + bo;
        }
    }
}

// ================= generic NT HMMA tf32: C[i,j] = sum_k A[i,k] B[j,k] =================
// 8 warps (4i x 2j), tile 128 x NJ. K chunks of 32, double-buffered smem stride 36.
// EPI 0: tf32(relu(acc*e1[j]+e2[j]))   EPI 1: tf32(acc + C0[i*ldc+j])
#define HS128 73728
#define HS64  55296

template<int NJ, int EPI>
__global__ void __launch_bounds__(256, 1) hmma_nt_g(
    const float* __restrict__ Ab, const float* __restrict__ Bb, float* __restrict__ Cb,
    int I, int K, int lda, int ldb, int ldc, int clampI,
    long long az, long long bz, long long cz,
    const float* __restrict__ C0, const float* __restrict__ e1, const float* __restrict__ e2)
{
    extern __shared__ float smf[];
    const int NI_ACC = NJ / 16;
    const int NB = NJ / 32;
    float* As = smf;                      // [2][128*36]
    float* Bs = smf + 2 * 128 * 36;       // [2][NJ*36]
    int t = threadIdx.x, lane = t & 31, w = t >> 5;
    int wn0 = (w & 3) * 32, wc0 = (w >> 2) * (NJ / 2);
    int g = lane >> 2, tq = lane & 3;
    int j0 = blockIdx.x * NJ, i0 = blockIdx.y * 128, b = blockIdx.z;
    const float* A = Ab + az * b;
    const float* B = Bb + bz * b;
    float* C = Cb + cz * b;
    int col4 = (t & 7) * 4, row0 = t >> 3;

    float acc[2][NI_ACC][4];
#pragma unroll
    for (int mi = 0; mi < 2; mi++)
#pragma unroll
        for (int ni = 0; ni < NI_ACC; ni++)
#pragma unroll
            for (int r = 0; r < 4; r++) acc[mi][ni][r] = 0.f;

    float4 ra[4], rb[NB];
    // chunk 0
#pragma unroll
    for (int i = 0; i < 4; i++) {
        int r = row0 + 32 * i;
        int ar = i0 + r; ar = ar < clampI ? ar : clampI - 1;
        ra[i] = *(const float4*)(A + (long long)ar * lda + col4);
    }
#pragma unroll
    for (int i = 0; i < NB; i++) {
        int r = row0 + 32 * i;
        rb[i] = *(const float4*)(B + (long long)(j0 + r) * ldb + col4);
    }
#pragma unroll
    for (int i = 0; i < 4; i++) { int r = row0 + 32 * i; *(float4*)&As[r * 36 + col4] = ra[i]; }
#pragma unroll
    for (int i = 0; i < NB; i++) { int r = row0 + 32 * i; *(float4*)&Bs[r * 36 + col4] = rb[i]; }
    __syncthreads();

    int nch = K / 32;
    for (int ch = 0; ch < nch; ch++) {
        int buf = ch & 1;
        bool more = (ch + 1) < nch;
        if (more) {
            int k0 = (ch + 1) * 32 + col4;
#pragma unroll
            for (int i = 0; i < 4; i++) {
                int r = row0 + 32 * i;
                int ar = i0 + r; ar = ar < clampI ? ar : clampI - 1;
                ra[i] = *(const float4*)(A + (long long)ar * lda + k0);
            }
#pragma unroll
            for (int i = 0; i < NB; i++) {
                int r = row0 + 32 * i;
                rb[i] = *(const float4*)(B + (long long)(j0 + r) * ldb + k0);
            }
        }
        const uint32_t* Asu = (const uint32_t*)(As + buf * 128 * 36);
        const uint32_t* Bsu = (const uint32_t*)(Bs + buf * NJ * 36);
#pragma unroll
        for (int ks = 0; ks < 4; ks++) {
            int kk = ks * 8 + tq;
            uint32_t a[2][4];
#pragma unroll
            for (int mi = 0; mi < 2; mi++) {
                int r = wn0 + 16 * mi + g;
                a[mi][0] = Asu[r * 36 + kk];
                a[mi][1] = Asu[(r + 8) * 36 + kk];
                a[mi][2] = Asu[r * 36 + kk + 4];
                a[mi][3] = Asu[(r + 8) * 36 + kk + 4];
            }
            uint32_t bf[NI_ACC][2];
#pragma unroll
            for (int ni = 0; ni < NI_ACC; ni++) {
                int c = wc0 + ni * 8 + g;
                bf[ni][0] = Bsu[c * 36 + kk];
                bf[ni][1] = Bsu[c * 36 + kk + 4];
            }
#pragma unroll
            for (int mi = 0; mi < 2; mi++)
#pragma unroll
                for (int ni = 0; ni < NI_ACC; ni++)
                    mma_tf32(acc[mi][ni], a[mi], bf[ni]);
        }
        if (more) {
            float* Ad = As + (buf ^ 1) * 128 * 36;
            float* Bd = Bs + (buf ^ 1) * NJ * 36;
#pragma unroll
            for (int i = 0; i < 4; i++) { int r = row0 + 32 * i; *(float4*)&Ad[r * 36 + col4] = ra[i]; }
#pragma unroll
            for (int i = 0; i < NB; i++) { int r = row0 + 32 * i; *(float4*)&Bd[r * 36 + col4] = rb[i]; }
        }
        __syncthreads();
    }

    // epilogue
#pragma unroll
    for (int mi = 0; mi < 2; mi++) {
#pragma unroll
        for (int ni = 0; ni < NI_ACC; ni++) {
            int jg = j0 + wc0 + ni * 8 + 2 * tq;
#pragma unroll
            for (int hh = 0; hh < 2; hh++) {
                int i = i0 + wn0 + 16 * mi + g + 8 * hh;
                if (i >= I) continue;
                float v0 = acc[mi][ni][2 * hh], v1 = acc[mi][ni][2 * hh + 1];
                if (EPI == 0) {
                    v0 = tf32_rna(fmaxf(v0 * e1[jg] + e2[jg], 0.f));
                    v1 = tf32_rna(fmaxf(v1 * e1[jg + 1] + e2[jg + 1], 0.f));
                } else {
                    long long ci = (long long)i * ldc + jg;
                    v0 = tf32_rna(v0 + C0[ci]);
                    v1 = tf32_rna(v1 + C0[ci + 1]);
                }
                *(float2*)(C + (long long)i * ldc + jg) = make_float2(v0, v1);
            }
        }
    }
}

// ================= logits HMMA: logits[b,h][n][m] = qt[n] . kt[m] (K=16) =================
__global__ void __launch_bounds__(256) logits_hmma(
    const float* __restrict__ qt, const float* __restrict__ kt, float* __restrict__ logits)
{
    __shared__ float As[128 * 20], Bs[128 * 20];
    int t = threadIdx.x, lane = t & 31, w = t >> 5;
    int wn0 = (w & 3) * 32, wc0 = (w >> 2) * 64;
    int g = lane >> 2, tq = lane & 3;
    int m0 = blockIdx.x * 128, n0 = blockIdx.y * 128;
    int z = blockIdx.z, b = z >> 2, h = z & 3;
    const float* Aq = qt + h * 16;
    const float* Bk = kt + (long long)b * MM * 64 + h * 16;
#pragma unroll
    for (int i = 0; i < 2; i++) {
        int gi = t + i * 256;
        int row = gi >> 2, gc = (gi & 3) * 4;
        int nr = n0 + row; nr = nr < NN ? nr : NN - 1;
        *(float4*)&As[row * 20 + gc] = *(const float4*)(Aq + (long long)nr * 64 + gc);
        *(float4*)&Bs[row * 20 + gc] = *(const float4*)(Bk + (long long)(m0 + row) * 64 + gc);
    }
    __syncthreads();
    float acc[2][8][4];
#pragma unroll
    for (int mi = 0; mi < 2; mi++)
#pragma unroll
        for (int ni = 0; ni < 8; ni++)
#pragma unroll
            for (int r = 0; r < 4; r++) acc[mi][ni][r] = 0.f;
    const uint32_t* Asu = (const uint32_t*)As;
    const uint32_t* Bsu = (const uint32_t*)Bs;
#pragma unroll
    for (int ks = 0; ks < 2; ks++) {
        int kk = ks * 8 + tq;
        uint32_t a[2][4];
#pragma unroll
        for (int mi = 0; mi < 2; mi++) {
            int r = wn0 + 16 * mi + g;
            a[mi][0] = Asu[r * 20 + kk];
            a[mi][1] = Asu[(r + 8) * 20 + kk];
            a[mi][2] = Asu[r * 20 + kk + 4];
            a[mi][3] = Asu[(r + 8) * 20 + kk + 4];
        }
        uint32_t bf[8][2];
#pragma unroll
        for (int ni = 0; ni < 8; ni++) {
            int c = wc0 + ni * 8 + g;
            bf[ni][0] = Bsu[c * 20 + kk];
            bf[ni][1] = Bsu[c * 20 + kk + 4];
        }
#pragma unroll
        for (int mi = 0; mi < 2; mi++)
#pragma unroll
            for (int ni = 0; ni < 8; ni++)
                mma_tf32(acc[mi][ni], a[mi], bf[ni]);
    }
    long long base = (long long)z * NN * MM;
#pragma unroll
    for (int mi = 0; mi < 2; mi++) {
#pragma unroll
        for (int ni = 0; ni < 8; ni++) {
            int m = m0 + wc0 + ni * 8 + 2 * tq;
#pragma unroll
            for (int hh = 0; hh < 2; hh++) {
                int n = n0 + wn0 + 16 * mi + g + 8 * hh;
                if (n < NN)
                    *(float2*)(logits + base + (long long)n * MM + m) =
                        make_float2(acc[mi][ni][2 * hh], acc[mi][ni][2 * hh + 1]);
            }
        }
    }
}

// ---------------- softmax; writes exact maps + tf32 attn_t ----------------
__global__ void softmax_kernel(const float* __restrict__ logits,
                               float* __restrict__ attn, float* __restrict__ attn_t,
                               float* __restrict__ invn)
{
    extern __shared__ float sm[];
    __shared__ float red[256];
    int bn = blockIdx.x;
    int b = bn / NN, n = bn - b * NN;
    int t = threadIdx.x;
#pragma unroll
    for (int h = 0; h < 4; h++) {
        const float* src = logits + ((long long)(b * 4 + h) * NN + n) * MM;
        for (int m = t; m < MM; m += 256) sm[h * MM + m] = src[m];
    }
    __syncthreads();
    float mx[4], rs[4];
#pragma unroll
    for (int h = 0; h < 4; h++) {
        float lm = -1e30f;
        for (int m = t; m < MM; m += 256) lm = fmaxf(lm, sm[h * MM + m]);
        red[t] = lm; __syncthreads();
        for (int k = 128; k > 0; k >>= 1) { if (t < k) red[t] = fmaxf(red[t], red[t + k]); __syncthreads(); }
        mx[h] = red[0]; __syncthreads();
        float ls = 0.f;
        for (int m = t; m < MM; m += 256) ls += __expf(sm[h * MM + m] - mx[h]);
        red[t] = ls; __syncthreads();
        for (int k = 128; k > 0; k >>= 1) { if (t < k) red[t] += red[t + k]; __syncthreads(); }
        rs[h] = 0.25f / red[0]; __syncthreads();
    }
    float ss = 0.f;
    float* dst  = attn + (long long)bn * MM;
    float* dstt = attn_t + (long long)bn * MM;
    for (int m = t; m < MM; m += 256) {
        float a = __expf(sm[m] - mx[0]) * rs[0]
                + __expf(sm[MM + m] - mx[1]) * rs[1]
                + __expf(sm[2 * MM + m] - mx[2]) * rs[2]
                + __expf(sm[3 * MM + m] - mx[3]) * rs[3];
        dst[m] = a; dstt[m] = tf32_rna(a); ss += a * a;
    }
    red[t] = ss; __syncthreads();
    for (int k = 128; k > 0; k >>= 1) { if (t < k) red[t] += red[t + k]; __syncthreads(); }
    if (t == 0) { float nr = sqrtf(red[0]); invn[bn] = 1.0f / fmaxf(nr, 1e-12f); }
}

// ---------------- diversity ----------------
__global__ void div_s_kernel(const float* __restrict__ attn, const float* __restrict__ invn)
{
    __shared__ float sinv[304];
    __shared__ float red[256];
    int b = blockIdx.y, t = threadIdx.x;
    for (int i = t; i < NN; i += 256) sinv[i] = invn[b * NN + i];
    __syncthreads();
    int m = blockIdx.x * 256 + t;
    const float* base = attn + (long long)b * NN * MM + m;
    float s = 0.f;
    for (int n = 0; n < NN; n++) s += base[(long long)n * MM] * sinv[n];
    red[t] = s * s; __syncthreads();
    for (int k = 128; k > 0; k >>= 1) { if (t < k) red[t] += red[t + k]; __syncthreads(); }
    if (t == 0) g_divpart[b * 16 + blockIdx.x] = red[0];
}

__global__ void finalize_div(float* __restrict__ outdiv)
{
    __shared__ float red[256];
    int t = threadIdx.x;
    red[t] = g_divpart[t]; __syncthreads();
    for (int k = 128; k > 0; k >>= 1) { if (t < k) red[t] += red[t + k]; __syncthreads(); }
    if (t == 0) outdiv[0] = (red[0] - (float)(BB * NN)) * (0.1f / ((float)NN * (NN - 1)));
}

// ---------------- LayerNorm(256) + ReLU, in place ----------------
__global__ void ln_relu_kernel(float* __restrict__ z, const float* __restrict__ g,
                               const float* __restrict__ bb)
{
    __shared__ float red[256];
    __shared__ float mu_s, var_s;
    int row = blockIdx.x, t = threadIdx.x;
    float v = z[(long long)row * 256 + t];
    red[t] = v; __syncthreads();
    for (int k = 128; k > 0; k >>= 1) { if (t < k) red[t] += red[t + k]; __syncthreads(); }
    if (t == 0) mu_s = red[0] * (1.0f / 256.0f);
    __syncthreads();
    float d = v - mu_s;
    red[t] = d * d; __syncthreads();
    for (int k = 128; k > 0; k >>= 1) { if (t < k) red[t] += red[t + k]; __syncthreads(); }
    if (t == 0) var_s = red[0] * (1.0f / 256.0f);
    __syncthreads();
    float o = d * rsqrtf(var_s + 1e-5f) * g[t] + bb[t];
    z[(long long)row * 256 + t] = fmaxf(o, 0.f);
}

// ---------------- SIMT GEMM NT (heads) ----------------
template<int EPI>
__global__ void __launch_bounds__(256) gemm_nt(
    const float* __restrict__ Ab, const float* __restrict__ Bb, float* __restrict__ Cb,
    int I, int J, int K, const float* __restrict__ bias)
{
    __shared__ float As[BK][TILE + 4];
    __shared__ float Bs[BK][TILE + 4];
    int t = threadIdx.x, tx = t & 15, ty = t >> 4;
    int iB = blockIdx.y * TILE, jB = blockIdx.x * TILE;

    float acc[8][8];
#pragma unroll
    for (int i = 0; i < 8; i++)
#pragma unroll
        for (int j = 0; j < 8; j++) acc[i][j] = 0.f;

    for (int k0 = 0; k0 < K; k0 += BK) {
#pragma unroll
        for (int r = 0; r < 2; r++) {
            int idx = t + r * 256;
            int row = idx >> 2, kq = (idx & 3) * 4;
            float4 v = make_float4(0.f, 0.f, 0.f, 0.f);
            int i = iB + row;
            if (i < I) v = *(const float4*)(Ab + (long long)i * K + k0 + kq);
            As[kq + 0][row] = v.x; As[kq + 1][row] = v.y;
            As[kq + 2][row] = v.z; As[kq + 3][row] = v.w;
        }
#pragma unroll
        for (int r = 0; r < 2; r++) {
            int idx = t + r * 256;
            int row = idx >> 2, kq = (idx & 3) * 4;
            float4 v = make_float4(0.f, 0.f, 0.f, 0.f);
            int j = jB + row;
            if (j < J) v = *(const float4*)(Bb + (long long)j * K + k0 + kq);
            Bs[kq + 0][row] = v.x; Bs[kq + 1][row] = v.y;
            Bs[kq + 2][row] = v.z; Bs[kq + 3][row] = v.w;
        }
        __syncthreads();
#pragma unroll
        for (int k = 0; k < BK; k++) {
            float a[8], bv[8];
            *(float4*)&a[0]  = *(const float4*)&As[k][ty * 4];
            *(float4*)&a[4]  = *(const float4*)&As[k][ty * 4 + 64];
            *(float4*)&bv[0] = *(const float4*)&Bs[k][tx * 4];
            *(float4*)&bv[4] = *(const float4*)&Bs[k][tx * 4 + 64];
#pragma unroll
            for (int i = 0; i < 8; i++)
#pragma unroll
                for (int j = 0; j < 8; j++) acc[i][j] += a[i] * bv[j];
        }
        __syncthreads();
    }
#pragma unroll
    for (int i = 0; i < 8; i++) {
        int ii = iB + (i < 4 ? ty * 4 + i : 64 + ty * 4 + i - 4);
        if (ii >= I) continue;
#pragma unroll
        for (int j = 0; j < 8; j++) {
            int jj = jB + (j < 4 ? tx * 4 + j : 64 + tx * 4 + j - 4);
            if (jj >= J) continue;
            float v = acc[i][j];
            if (bias) v += bias[jj];
            if (EPI == 1) v = fmaxf(v, 0.f);
            else if (EPI == 2) v = 1.0f / (1.0f + __expf(-v));
            Cb[(long long)ii * J + jj] = v;
        }
    }
}

// ================= sf = attn @ vals^T (R3 structure, pre-rounded operands) =================
#define SF_ROWF 36
#define SF_BUF  (128 * SF_ROWF)
#define SF_SMEM (4 * SF_BUF * 4)

__global__ void __launch_bounds__(256, 1) sf_hmma_kernel(
    const float* __restrict__ attn_t, const float* __restrict__ vals,
    float* __restrict__ sfb, float* __restrict__ outsf)
{
    extern __shared__ float smf[];
    float* As = smf;
    float* Bs = smf + 2 * SF_BUF;
    int t = threadIdx.x;
    int lane = t & 31, w = t >> 5;
    int wn0 = (w & 3) * 32, wc0 = (w >> 2) * 64;
    int g = lane >> 2, tq = lane & 3;
    int n0 = blockIdx.y * 128, c0 = blockIdx.x * 128, b = blockIdx.z;

    int col4 = (t & 7) * 4;
    int row0 = t >> 3;

    const float* Ab = attn_t + (long long)b * NN * MM;
    const float* Bb = vals + (long long)b * HID * MM;

    float acc[2][8][4];
#pragma unroll
    for (int mi = 0; mi < 2; mi++)
#pragma unroll
        for (int ni = 0; ni < 8; ni++)
#pragma unroll
            for (int r = 0; r < 4; r++) acc[mi][ni][r] = 0.f;

    float4 ra[4], rb[4];
#pragma unroll
    for (int i = 0; i < 4; i++) {
        int r = row0 + 32 * i;
        int an = n0 + r; if (an > NN - 1) an = NN - 1;
        ra[i] = *(const float4*)(Ab + (long long)an * MM + col4);
        rb[i] = *(const float4*)(Bb + (long long)(c0 + r) * MM + col4);
    }
#pragma unroll
    for (int i = 0; i < 4; i++) {
        int r = row0 + 32 * i;
        *(float4*)&As[r * SF_ROWF + col4] = ra[i];
        *(float4*)&Bs[r * SF_ROWF + col4] = rb[i];
    }
    __syncthreads();

    for (int ch = 0; ch < MM / 32; ch++) {
        int buf = ch & 1;
        bool more = (ch + 1) < MM / 32;
        if (more) {
            int k0 = (ch + 1) * 32 + col4;
#pragma unroll
            for (int i = 0; i < 4; i++) {
                int r = row0 + 32 * i;
                int an = n0 + r; if (an > NN - 1) an = NN - 1;
                ra[i] = *(const float4*)(Ab + (long long)an * MM + k0);
                rb[i] = *(const float4*)(Bb + (long long)(c0 + r) * MM + k0);
            }
        }
        const uint32_t* Asu = (const uint32_t*)(As + buf * SF_BUF);
        const uint32_t* Bsu = (const uint32_t*)(Bs + buf * SF_BUF);
#pragma unroll
        for (int ks = 0; ks < 4; ks++) {
            int kk = ks * 8 + tq;
            uint32_t a[2][4];
#pragma unroll
            for (int mi = 0; mi < 2; mi++) {
                int r = wn0 + 16 * mi + g;
                a[mi][0] = Asu[r * SF_ROWF + kk];
                a[mi][1] = Asu[(r + 8) * SF_ROWF + kk];
                a[mi][2] = Asu[r * SF_ROWF + kk + 4];
                a[mi][3] = Asu[(r + 8) * SF_ROWF + kk + 4];
            }
            uint32_t bf[8][2];
#pragma unroll
            for (int ni = 0; ni < 8; ni++) {
                int c = wc0 + ni * 8 + g;
                bf[ni][0] = Bsu[c * SF_ROWF + kk];
                bf[ni][1] = Bsu[c * SF_ROWF + kk + 4];
            }
#pragma unroll
            for (int mi = 0; mi < 2; mi++)
#pragma unroll
                for (int ni = 0; ni < 8; ni++)
                    mma_tf32(acc[mi][ni], a[mi], bf[ni]);
        }
        if (more) {
            float* Ad = As + (buf ^ 1) * SF_BUF;
            float* Bd = Bs + (buf ^ 1) * SF_BUF;
#pragma unroll
            for (int i = 0; i < 4; i++) {
                int r = row0 + 32 * i;
                *(float4*)&Ad[r * SF_ROWF + col4] = ra[i];
                *(float4*)&Bd[r * SF_ROWF + col4] = rb[i];
            }
        }
        __syncthreads();
    }

#pragma unroll
    for (int mi = 0; mi < 2; mi++) {
#pragma unroll
        for (int ni = 0; ni < 8; ni++) {
            int c = c0 + wc0 + ni * 8 + 2 * tq;
#pragma unroll
            for (int hh = 0; hh < 2; hh++) {
                int n1 = n0 + wn0 + 16 * mi + g + 8 * hh;
                if (n1 < NN) {
                    long long o = ((long long)b * NN + n1) * HID + c;
                    float2 v = make_float2(acc[mi][ni][2 * hh], acc[mi][ni][2 * hh + 1]);
                    *(float2*)(sfb + o) = v;
                    outsf[o] = v.x; outsf[o + 1] = v.y;
                }
            }
        }
    }
}

// ---------------- host ----------------
extern "C" void kernel_launch(void* const* d_in, const int* in_sizes, int n_in,
                              void* d_out_, int out_size)
{
    const float* x      = (const float*)d_in[0];
    const float* q      = (const float*)d_in[1];
    const float* pos_w  = (const float*)d_in[2];
    const float* pos_b  = (const float*)d_in[3];
    const float* fp_w   = (const float*)d_in[4];
    const float* fp_b   = (const float*)d_in[5];
    const float* bn_g   = (const float*)d_in[6];
    const float* bn_b   = (const float*)d_in[7];
    const float* bn_m   = (const float*)d_in[8];
    const float* bn_v   = (const float*)d_in[9];
    const float* key_w  = (const float*)d_in[10];
    const float* key_b  = (const float*)d_in[11];
    const float* val_w  = (const float*)d_in[12];
    const float* val_b  = (const float*)d_in[13];
    const float* ctp_w  = (const float*)d_in[14];
    const float* ctp_b  = (const float*)d_in[15];
    const float* bb1_w  = (const float*)d_in[16];
    const float* bb1_b  = (const float*)d_in[17];
    const float* bbln_g = (const float*)d_in[18];
    const float* bbln_b = (const float*)d_in[19];
    const float* bb2_w  = (const float*)d_in[20];
    const float* bb2_b  = (const float*)d_in[21];
    const float* bb3_w  = (const float*)d_in[22];
    const float* bb3_b  = (const float*)d_in[23];
    const float* ch1_w  = (const float*)d_in[24];
    const float* ch1_b  = (const float*)d_in[25];
    const float* chln_g = (const float*)d_in[26];
    const float* chln_b = (const float*)d_in[27];
    const float* ch2_w  = (const float*)d_in[28];
    const float* ch2_b  = (const float*)d_in[29];
    const float* ch3_w  = (const float*)d_in[30];
    const float* ch3_b  = (const float*)d_in[31];
    float* out = (float*)d_out_;

    float *ft, *kt, *vals, *pos, *posk, *poskt, *posv, *logits, *attn_t, *invn, *sfb,
          *h1, *h2, *bns, *bnt, *fpwt, *keywt, *valwt, *qt;
    cudaGetSymbolAddress((void**)&ft,     g_ft);
    cudaGetSymbolAddress((void**)&kt,     g_kt);
    cudaGetSymbolAddress((void**)&vals,   g_vals);
    cudaGetSymbolAddress((void**)&pos,    g_pos);
    cudaGetSymbolAddress((void**)&posk,   g_posk);
    cudaGetSymbolAddress((void**)&poskt,  g_poskt);
    cudaGetSymbolAddress((void**)&posv,   g_posv);
    cudaGetSymbolAddress((void**)&logits, g_logits);
    cudaGetSymbolAddress((void**)&attn_t, g_attn_t);
    cudaGetSymbolAddress((void**)&invn,   g_invn);
    cudaGetSymbolAddress((void**)&sfb,    g_sf);
    cudaGetSymbolAddress((void**)&h1,     g_h1);
    cudaGetSymbolAddress((void**)&h2,     g_h2);
    cudaGetSymbolAddress((void**)&bns,    g_bns);
    cudaGetSymbolAddress((void**)&bnt,    g_bnt);
    cudaGetSymbolAddress((void**)&fpwt,   g_fpwt);
    cudaGetSymbolAddress((void**)&keywt,  g_keywt);
    cudaGetSymbolAddress((void**)&valwt,  g_valwt);
    cudaGetSymbolAddress((void**)&qt,     g_qt);
    float* xt = logits;  // alias: xt consumed before logits written (stream-ordered)

    cudaFuncSetAttribute(softmax_kernel, cudaFuncAttributeMaxDynamicSharedMemorySize, 4 * MM * 4);
    cudaFuncSetAttribute(sf_hmma_kernel, cudaFuncAttributeMaxDynamicSharedMemorySize, SF_SMEM);
    cudaFuncSetAttribute(hmma_nt_g<128, 0>, cudaFuncAttributeMaxDynamicSharedMemorySize, HS128);
    cudaFuncSetAttribute(hmma_nt_g<128, 1>, cudaFuncAttributeMaxDynamicSharedMemorySize, HS128);
    cudaFuncSetAttribute(hmma_nt_g<64, 1>,  cudaFuncAttributeMaxDynamicSharedMemorySize, HS64);

    // 1. BN fold + tf32 weight copies
    init_kernel<<<1, 128>>>(fp_b, bn_g, bn_b, bn_m, bn_v);
    round_kernel<<<128, 256>>>(fp_w, fpwt, 128 * 256, 1.f);
    round_kernel<<<64, 256>>>(key_w, keywt, 64 * 256, 1.f);
    round_kernel<<<256, 256>>>(val_w, valwt, 256 * 256, 1.f);
    round_kernel<<<75, 256>>>(q, qt, NN * 64, 0.25f);
    // 2. positional channels + pos contributions (SIMT, batch-invariant)
    pos_kernel<<<dim3(16, 128), 256>>>(pos_w, pos_b);
    gemm_nn_pos<<<dim3(32, 1, 1), 256>>>(key_w + 128, 256, pos, posk, 64, MM, 128, key_b);
    gemm_nn_pos<<<dim3(32, 2, 1), 256>>>(val_w + 128, 256, pos, posv, 256, MM, 128, val_b);
    transpose_kernel<false><<<dim3(128, 2, 1), dim3(32, 8)>>>(posk, poskt, 64, MM, 0, 0);
    // 3. x transpose (tf32-rounded): xt[b][m][256]
    transpose_kernel<true><<<dim3(128, 8, BB), dim3(32, 8)>>>(x, xt, CC, MM,
                                                              (long long)CC * MM, (long long)MM * CC);
    // 4. ft[b][m][128] = tf32(relu(bn(xt @ fp_w^T)))
    hmma_nt_g<128, 0><<<dim3(1, 32, BB), 256, HS128>>>(xt, fpwt, ft,
        MM, 256, 256, 256, 128, MM, (long long)MM * 256, 0, (long long)MM * 128,
        nullptr, bns, bnt);
    // 5. kt[b][m][64] = tf32(ft @ key_w[:, :128]^T + poskt)
    hmma_nt_g<64, 1><<<dim3(1, 32, BB), 256, HS64>>>(ft, keywt, kt,
        MM, 128, 128, 256, 64, MM, (long long)MM * 128, 0, (long long)MM * 64,
        poskt, nullptr, nullptr);
    // 6. vals[b][c][m] = tf32(val_w[:, :128] @ ft^T + posv)
    hmma_nt_g<128, 1><<<dim3(32, 2, BB), 256, HS128>>>(valwt, ft, vals,
        256, 128, 256, 128, MM, 256, 0, (long long)MM * 128, (long long)MM * 256,
        posv, nullptr, nullptr);
    // 7. logits (K=16 HMMA; q pre-scaled by 0.25)
    logits_hmma<<<dim3(32, 3, BB * 4), 256>>>(qt, kt, logits);
    // 8. softmax: exact maps -> d_out, tf32 attn_t -> scratch
    softmax_kernel<<<BB * NN, 256, 4 * MM * 4>>>(logits, out + OFF_MAPS, attn_t, invn);
    // 9. diversity
    div_s_kernel<<<dim3(16, BB), 256>>>(out + OFF_MAPS, invn);
    finalize_div<<<1, 256>>>(out + OFF_DIV);
    // 10. sf = attn @ vals^T
    sf_hmma_kernel<<<dim3(2, 3, BB), 256, SF_SMEM>>>(attn_t, vals, sfb, out + OFF_SF);
    // 11. box head
    gemm_nt<0><<<dim3(2, 38, 1), 256>>>(sfb, bb1_w, h1, BB * NN, 256, 256, bb1_b);
    ln_relu_kernel<<<BB * NN, 256>>>(h1, bbln_g, bbln_b);
    gemm_nt<1><<<dim3(1, 38, 1), 256>>>(h1, bb2_w, h2, BB * NN, 128, 256, bb2_b);
    gemm_nt<0><<<dim3(1, 38, 1), 256>>>(h2, bb3_w, out + OFF_BOXES, BB * NN, 4, 128, bb3_b);
    // 12. score head
    gemm_nt<0><<<dim3(2, 38, 1), 256>>>(sfb, ch1_w, h1, BB * NN, 256, 256, ch1_b);
    ln_relu_kernel<<<BB * NN, 256>>>(h1, chln_g, chln_b);
    gemm_nt<1><<<dim3(1, 38, 1), 256>>>(h1, ch2_w, h2, BB * NN, 128, 256, ch2_b);
    gemm_nt<2><<<dim3(1, 38, 1), 256>>>(h2, ch3_w, out + OFF_SCORES, BB * NN, 1, 128, ch3_b);
    // 13. class head
    gemm_nt<0><<<dim3(1, 38, 1), 256>>>(sfb, ctp_w, out + OFF_CLS, BB * NN, NCC, 256, ctp_b);
}

// round 7
// speedup vs baseline: 1.5456x; 1.2211x over previous
#include <cuda_runtime.h>
#include <cstdint>
#include <math.h>

// ---------------- problem constants ----------------
#define BB   16
#define CC   256
#define MM   4096          // H*W
#define HID  256
#define NN   300
#define NCC  80

// output layout (flattened tuple: boxes, scores, cls, maps, div, sf)
#define OFF_BOXES  0LL
#define OFF_SCORES 19200LL
#define OFF_CLS    24000LL
#define OFF_MAPS   408000LL
#define OFF_DIV    20068800LL
#define OFF_SF     20068801LL

// ---------------- device scratch ----------------
__device__ float g_ft   [BB * 128 * MM];
__device__ float g_kt   [BB * 64 * MM];
__device__ float g_vals [BB * 256 * MM];
__device__ float g_pos  [128 * MM];
__device__ float g_posk [64 * MM];
__device__ float g_poskt[MM * 64];
__device__ float g_posv [256 * MM];
__device__ float g_logits[(long long)BB * 4 * NN * MM]; // also aliases xt
__device__ float g_attn_t[(long long)BB * NN * MM];
__device__ float g_invn [BB * NN];
__device__ float g_sf   [BB * NN * HID];                // tf32-rounded copy for heads
__device__ float g_h1   [BB * NN * 256];
__device__ float g_h2   [BB * NN * 128];
__device__ float g_bns  [128];
__device__ float g_bnt  [128];
__device__ float g_divpart[256];
__device__ float g_fpwt [128 * 256];
__device__ float g_keywt[64 * 256];
__device__ float g_valwt[256 * 256];
__device__ float g_qt   [NN * 64];
__device__ float g_hbb1 [256 * 256];
__device__ float g_hch1 [256 * 256];
__device__ float g_hbb2 [128 * 256];
__device__ float g_hch2 [128 * 256];

__device__ __forceinline__ float tf32_rna(float v) {
    uint32_t u;
    asm("cvt.rna.tf32.f32 %0, %1;" : "=r"(u) : "f"(v));
    return __uint_as_float(u);
}
__device__ __forceinline__ void mma_tf32(float c[4], const uint32_t a[4], const uint32_t b[2]) {
    asm volatile(
        "mma.sync.aligned.m16n8k8.row.col.f32.tf32.tf32.f32 "
        "{%0,%1,%2,%3}, {%4,%5,%6,%7}, {%8,%9}, {%0,%1,%2,%3};"
        : "+f"(c[0]), "+f"(c[1]), "+f"(c[2]), "+f"(c[3])
        : "r"(a[0]), "r"(a[1]), "r"(a[2]), "r"(a[3]), "r"(b[0]), "r"(b[1]));
}

// ---------------- small kernels ----------------
__global__ void init_kernel(const float* __restrict__ fp_b, const float* __restrict__ bn_g,
                            const float* __restrict__ bn_b, const float* __restrict__ bn_m,
                            const float* __restrict__ bn_v) {
    int t = threadIdx.x;
    if (t < 128) {
        float s = bn_g[t] * rsqrtf(bn_v[t] + 1e-5f);
        g_bns[t] = s;
        g_bnt[t] = (fp_b[t] - bn_m[t]) * s + bn_b[t];
    }
}

struct RoundJob { const float* s; float* d; int n; float sc; };
struct RoundJobs { RoundJob j[8]; };
__global__ void round_many(RoundJobs jobs) {
    int tid = blockIdx.x * 256 + threadIdx.x;
    int stride = gridDim.x * 256;
#pragma unroll
    for (int k = 0; k < 8; k++) {
        const RoundJob J = jobs.j[k];
        for (int i = tid; i < J.n; i += stride) J.d[i] = tf32_rna(J.s[i] * J.sc);
    }
}

__global__ void pos_kernel(const float* __restrict__ pos_w, const float* __restrict__ pos_b) {
    int m = blockIdx.x * 256 + threadIdx.x;
    int o = blockIdx.y;
    int hh = m >> 6, ww = m & 63;
    float y = -1.0f + 2.0f * (float)hh / 63.0f;
    float x = -1.0f + 2.0f * (float)ww / 63.0f;
    g_pos[(long long)o * MM + m] = pos_w[o * 2] * y + pos_w[o * 2 + 1] * x + pos_b[o];
}

template<bool RND>
__global__ void transpose_kernel(const float* __restrict__ src, float* __restrict__ dst,
                                 int rows, int cols, long long zsrc, long long zdst)
{
    __shared__ float tile[32][33];
    int b = blockIdx.z;
    const float* s = src + zsrc * b;
    float* d = dst + zdst * b;
    int c0 = blockIdx.x * 32, r0 = blockIdx.y * 32;
    int tx = threadIdx.x, ty = threadIdx.y;
#pragma unroll
    for (int k = 0; k < 4; k++)
        tile[ty + 8 * k][tx] = s[(long long)(r0 + ty + 8 * k) * cols + c0 + tx];
    __syncthreads();
#pragma unroll
    for (int k = 0; k < 4; k++) {
        float v = tile[tx][ty + 8 * k];
        if (RND) v = tf32_rna(v);
        d[(long long)(c0 + ty + 8 * k) * rows + r0 + tx] = v;
    }
}

// ---------------- SIMT GEMM NN (pos contributions only) ----------------
#define TILE 128
#define BK   16

__global__ void __launch_bounds__(256) gemm_nn_pos(
    const float* __restrict__ W, int ldw,
    const float* __restrict__ X, float* __restrict__ C,
    int O, int M, int K, const float* __restrict__ bias)
{
    __shared__ float Ws[BK][TILE + 4];
    __shared__ float Xs[BK][TILE + 4];
    int t = threadIdx.x, tx = t & 15, ty = t >> 4;
    int oB = blockIdx.y * TILE, mB = blockIdx.x * TILE;

    float acc[8][8];
#pragma unroll
    for (int i = 0; i < 8; i++)
#pragma unroll
        for (int j = 0; j < 8; j++) acc[i][j] = 0.f;

    for (int k0 = 0; k0 < K; k0 += BK) {
#pragma unroll
        for (int r = 0; r < 2; r++) {
            int idx = t + r * 256;
            int row = idx >> 2, kq = (idx & 3) * 4;
            float4 v = make_float4(0.f, 0.f, 0.f, 0.f);
            int o = oB + row;
            if (o < O) v = *(const float4*)(W + (long long)o * ldw + k0 + kq);
            Ws[kq + 0][row] = v.x; Ws[kq + 1][row] = v.y;
            Ws[kq + 2][row] = v.z; Ws[kq + 3][row] = v.w;
        }
#pragma unroll
        for (int r = 0; r < 2; r++) {
            int idx = t + r * 256;
            int row = idx >> 5, cq = (idx & 31) * 4;
            float4 v = *(const float4*)(X + (long long)(k0 + row) * M + mB + cq);
            *(float4*)&Xs[row][cq] = v;
        }
        __syncthreads();
#pragma unroll
        for (int k = 0; k < BK; k++) {
            float a[8], bv[8];
            *(float4*)&a[0]  = *(const float4*)&Ws[k][ty * 4];
            *(float4*)&a[4]  = *(const float4*)&Ws[k][ty * 4 + 64];
            *(float4*)&bv[0] = *(const float4*)&Xs[k][tx * 4];
            *(float4*)&bv[4] = *(const float4*)&Xs[k][tx * 4 + 64];
#pragma unroll
            for (int i = 0; i < 8; i++)
#pragma unroll
                for (int j = 0; j < 8; j++) acc[i][j] += a[i] * bv[j];
        }
        __syncthreads();
    }
#pragma unroll
    for (int i = 0; i < 8; i++) {
        int o = oB + (i < 4 ? ty * 4 + i : 64 + ty * 4 + i - 4);
        if (o >= O) continue;
        float bo = bias[o];
#pragma unroll
        for (int j = 0; j < 8; j++) {
            int m = mB + (j < 4 ? tx * 4 + j : 64 + tx * 4 + j - 4);
            C[(long long)o * M + m] = acc[i][j] + bo;
        }
    }
}

// ================= generic NT HMMA tf32 =================
// EPI 0: tf32(relu(acc*e1[j]+e2[j]))  EPI 1: tf32(acc+C0)  EPI 2: acc+e1[j]  EPI 3: relu(acc+e1[j])
#define HS128 73728
#define HS64  55296

template<int NJ, int EPI>
__global__ void __launch_bounds__(256, 1) hmma_nt_g(
    const float* __restrict__ Ab, const float* __restrict__ Bb, float* __restrict__ Cb,
    int I, int K, int lda, int ldb, int ldc, int clampI,
    long long az, long long bz, long long cz,
    const float* __restrict__ C0, const float* __restrict__ e1, const float* __restrict__ e2)
{
    extern __shared__ float smf[];
    const int NI_ACC = NJ / 16;
    const int NB = NJ / 32;
    float* As = smf;
    float* Bs = smf + 2 * 128 * 36;
    int t = threadIdx.x, lane = t & 31, w = t >> 5;
    int wn0 = (w & 3) * 32, wc0 = (w >> 2) * (NJ / 2);
    int g = lane >> 2, tq = lane & 3;
    int j0 = blockIdx.x * NJ, i0 = blockIdx.y * 128, b = blockIdx.z;
    const float* A = Ab + az * b;
    const float* B = Bb + bz * b;
    float* C = Cb + cz * b;
    int col4 = (t & 7) * 4, row0 = t >> 3;

    float acc[2][NI_ACC][4];
#pragma unroll
    for (int mi = 0; mi < 2; mi++)
#pragma unroll
        for (int ni = 0; ni < NI_ACC; ni++)
#pragma unroll
            for (int r = 0; r < 4; r++) acc[mi][ni][r] = 0.f;

    float4 ra[4], rb[NB];
#pragma unroll
    for (int i = 0; i < 4; i++) {
        int r = row0 + 32 * i;
        int ar = i0 + r; ar = ar < clampI ? ar : clampI - 1;
        ra[i] = *(const float4*)(A + (long long)ar * lda + col4);
    }
#pragma unroll
    for (int i = 0; i < NB; i++) {
        int r = row0 + 32 * i;
        rb[i] = *(const float4*)(B + (long long)(j0 + r) * ldb + col4);
    }
#pragma unroll
    for (int i = 0; i < 4; i++) { int r = row0 + 32 * i; *(float4*)&As[r * 36 + col4] = ra[i]; }
#pragma unroll
    for (int i = 0; i < NB; i++) { int r = row0 + 32 * i; *(float4*)&Bs[r * 36 + col4] = rb[i]; }
    __syncthreads();

    int nch = K / 32;
    for (int ch = 0; ch < nch; ch++) {
        int buf = ch & 1;
        bool more = (ch + 1) < nch;
        if (more) {
            int k0 = (ch + 1) * 32 + col4;
#pragma unroll
            for (int i = 0; i < 4; i++) {
                int r = row0 + 32 * i;
                int ar = i0 + r; ar = ar < clampI ? ar : clampI - 1;
                ra[i] = *(const float4*)(A + (long long)ar * lda + k0);
            }
#pragma unroll
            for (int i = 0; i < NB; i++) {
                int r = row0 + 32 * i;
                rb[i] = *(const float4*)(B + (long long)(j0 + r) * ldb + k0);
            }
        }
        const uint32_t* Asu = (const uint32_t*)(As + buf * 128 * 36);
        const uint32_t* Bsu = (const uint32_t*)(Bs + buf * NJ * 36);
#pragma unroll
        for (int ks = 0; ks < 4; ks++) {
            int kk = ks * 8 + tq;
            uint32_t a[2][4];
#pragma unroll
            for (int mi = 0; mi < 2; mi++) {
                int r = wn0 + 16 * mi + g;
                a[mi][0] = Asu[r * 36 + kk];
                a[mi][1] = Asu[(r + 8) * 36 + kk];
                a[mi][2] = Asu[r * 36 + kk + 4];
                a[mi][3] = Asu[(r + 8) * 36 + kk + 4];
            }
            uint32_t bf[NI_ACC][2];
#pragma unroll
            for (int ni = 0; ni < NI_ACC; ni++) {
                int c = wc0 + ni * 8 + g;
                bf[ni][0] = Bsu[c * 36 + kk];
                bf[ni][1] = Bsu[c * 36 + kk + 4];
            }
#pragma unroll
            for (int mi = 0; mi < 2; mi++)
#pragma unroll
                for (int ni = 0; ni < NI_ACC; ni++)
                    mma_tf32(acc[mi][ni], a[mi], bf[ni]);
        }
        if (more) {
            float* Ad = As + (buf ^ 1) * 128 * 36;
            float* Bd = Bs + (buf ^ 1) * NJ * 36;
#pragma unroll
            for (int i = 0; i < 4; i++) { int r = row0 + 32 * i; *(float4*)&Ad[r * 36 + col4] = ra[i]; }
#pragma unroll
            for (int i = 0; i < NB; i++) { int r = row0 + 32 * i; *(float4*)&Bd[r * 36 + col4] = rb[i]; }
        }
        __syncthreads();
    }

#pragma unroll
    for (int mi = 0; mi < 2; mi++) {
#pragma unroll
        for (int ni = 0; ni < NI_ACC; ni++) {
            int jg = j0 + wc0 + ni * 8 + 2 * tq;
#pragma unroll
            for (int hh = 0; hh < 2; hh++) {
                int i = i0 + wn0 + 16 * mi + g + 8 * hh;
                if (i >= I) continue;
                float v0 = acc[mi][ni][2 * hh], v1 = acc[mi][ni][2 * hh + 1];
                if (EPI == 0) {
                    v0 = tf32_rna(fmaxf(v0 * e1[jg] + e2[jg], 0.f));
                    v1 = tf32_rna(fmaxf(v1 * e1[jg + 1] + e2[jg + 1], 0.f));
                } else if (EPI == 1) {
                    long long ci = (long long)i * ldc + jg;
                    v0 = tf32_rna(v0 + C0[ci]);
                    v1 = tf32_rna(v1 + C0[ci + 1]);
                } else if (EPI == 2) {
                    v0 = v0 + e1[jg]; v1 = v1 + e1[jg + 1];
                } else {
                    v0 = fmaxf(v0 + e1[jg], 0.f); v1 = fmaxf(v1 + e1[jg + 1], 0.f);
                }
                *(float2*)(C + (long long)i * ldc + jg) = make_float2(v0, v1);
            }
        }
    }
}

// ================= logits HMMA (K=16) =================
__global__ void __launch_bounds__(256) logits_hmma(
    const float* __restrict__ qt, const float* __restrict__ kt, float* __restrict__ logits)
{
    __shared__ float As[128 * 20], Bs[128 * 20];
    int t = threadIdx.x, lane = t & 31, w = t >> 5;
    int wn0 = (w & 3) * 32, wc0 = (w >> 2) * 64;
    int g = lane >> 2, tq = lane & 3;
    int m0 = blockIdx.x * 128, n0 = blockIdx.y * 128;
    int z = blockIdx.z, b = z >> 2, h = z & 3;
    const float* Aq = qt + h * 16;
    const float* Bk = kt + (long long)b * MM * 64 + h * 16;
#pragma unroll
    for (int i = 0; i < 2; i++) {
        int gi = t + i * 256;
        int row = gi >> 2, gc = (gi & 3) * 4;
        int nr = n0 + row; nr = nr < NN ? nr : NN - 1;
        *(float4*)&As[row * 20 + gc] = *(const float4*)(Aq + (long long)nr * 64 + gc);
        *(float4*)&Bs[row * 20 + gc] = *(const float4*)(Bk + (long long)(m0 + row) * 64 + gc);
    }
    __syncthreads();
    float acc[2][8][4];
#pragma unroll
    for (int mi = 0; mi < 2; mi++)
#pragma unroll
        for (int ni = 0; ni < 8; ni++)
#pragma unroll
            for (int r = 0; r < 4; r++) acc[mi][ni][r] = 0.f;
    const uint32_t* Asu = (const uint32_t*)As;
    const uint32_t* Bsu = (const uint32_t*)Bs;
#pragma unroll
    for (int ks = 0; ks < 2; ks++) {
        int kk = ks * 8 + tq;
        uint32_t a[2][4];
#pragma unroll
        for (int mi = 0; mi < 2; mi++) {
            int r = wn0 + 16 * mi + g;
            a[mi][0] = Asu[r * 20 + kk];
            a[mi][1] = Asu[(r + 8) * 20 + kk];
            a[mi][2] = Asu[r * 20 + kk + 4];
            a[mi][3] = Asu[(r + 8) * 20 + kk + 4];
        }
        uint32_t bf[8][2];
#pragma unroll
        for (int ni = 0; ni < 8; ni++) {
            int c = wc0 + ni * 8 + g;
            bf[ni][0] = Bsu[c * 20 + kk];
            bf[ni][1] = Bsu[c * 20 + kk + 4];
        }
#pragma unroll
        for (int mi = 0; mi < 2; mi++)
#pragma unroll
            for (int ni = 0; ni < 8; ni++)
                mma_tf32(acc[mi][ni], a[mi], bf[ni]);
    }
    long long base = (long long)z * NN * MM;
#pragma unroll
    for (int mi = 0; mi < 2; mi++) {
#pragma unroll
        for (int ni = 0; ni < 8; ni++) {
            int m = m0 + wc0 + ni * 8 + 2 * tq;
#pragma unroll
            for (int hh = 0; hh < 2; hh++) {
                int n = n0 + wn0 + 16 * mi + g + 8 * hh;
                if (n < NN)
                    *(float2*)(logits + base + (long long)n * MM + m) =
                        make_float2(acc[mi][ni][2 * hh], acc[mi][ni][2 * hh + 1]);
            }
        }
    }
}

// ---------------- register-resident softmax ----------------
__global__ void __launch_bounds__(256) softmax_kernel(
    const float* __restrict__ logits,
    float* __restrict__ attn, float* __restrict__ attn_t,
    float* __restrict__ invn)
{
    __shared__ float red[40];
    int bn = blockIdx.x;
    int b = bn / NN, n = bn - b * NN;
    int t = threadIdx.x, lane = t & 31, wid = t >> 5;
    float v[4][16];
#pragma unroll
    for (int h = 0; h < 4; h++) {
        const float* src = logits + ((long long)(b * 4 + h) * NN + n) * MM;
#pragma unroll
        for (int k = 0; k < 16; k++) v[h][k] = src[t + 256 * k];
    }
    // per-head max
    float lm[4];
#pragma unroll
    for (int h = 0; h < 4; h++) {
        float m = v[h][0];
#pragma unroll
        for (int k = 1; k < 16; k++) m = fmaxf(m, v[h][k]);
#pragma unroll
        for (int s = 16; s > 0; s >>= 1) m = fmaxf(m, __shfl_xor_sync(0xFFFFFFFFu, m, s));
        lm[h] = m;
    }
    if (lane == 0) {
#pragma unroll
        for (int h = 0; h < 4; h++) red[wid * 4 + h] = lm[h];
    }
    __syncthreads();
    if (t < 32) {
        float x = red[t];
        x = fmaxf(x, __shfl_xor_sync(0xFFFFFFFFu, x, 4));
        x = fmaxf(x, __shfl_xor_sync(0xFFFFFFFFu, x, 8));
        x = fmaxf(x, __shfl_xor_sync(0xFFFFFFFFu, x, 16));
        if (t < 4) red[32 + t] = x;
    }
    __syncthreads();
    float mx[4];
#pragma unroll
    for (int h = 0; h < 4; h++) mx[h] = red[32 + h];
    // exp + sum
    float ls[4];
#pragma unroll
    for (int h = 0; h < 4; h++) {
        float s = 0.f;
#pragma unroll
        for (int k = 0; k < 16; k++) {
            float e = __expf(v[h][k] - mx[h]);
            v[h][k] = e; s += e;
        }
#pragma unroll
        for (int st = 16; st > 0; st >>= 1) s += __shfl_xor_sync(0xFFFFFFFFu, s, st);
        ls[h] = s;
    }
    __syncthreads();
    if (lane == 0) {
#pragma unroll
        for (int h = 0; h < 4; h++) red[wid * 4 + h] = ls[h];
    }
    __syncthreads();
    if (t < 32) {
        float x = red[t];
        x += __shfl_xor_sync(0xFFFFFFFFu, x, 4);
        x += __shfl_xor_sync(0xFFFFFFFFu, x, 8);
        x += __shfl_xor_sync(0xFFFFFFFFu, x, 16);
        if (t < 4) red[36 + t] = 0.25f / x;
    }
    __syncthreads();
    float rs[4];
#pragma unroll
    for (int h = 0; h < 4; h++) rs[h] = red[36 + h];
    // combine + write
    float ss = 0.f;
    float* dst  = attn + (long long)bn * MM;
    float* dstt = attn_t + (long long)bn * MM;
#pragma unroll
    for (int k = 0; k < 16; k++) {
        float a = v[0][k] * rs[0] + v[1][k] * rs[1] + v[2][k] * rs[2] + v[3][k] * rs[3];
        int m = t + 256 * k;
        dst[m] = a; dstt[m] = tf32_rna(a); ss += a * a;
    }
#pragma unroll
    for (int st = 16; st > 0; st >>= 1) ss += __shfl_xor_sync(0xFFFFFFFFu, ss, st);
    __syncthreads();
    if (lane == 0) red[wid] = ss;
    __syncthreads();
    if (t == 0) {
        float s = 0.f;
#pragma unroll
        for (int i = 0; i < 8; i++) s += red[i];
        invn[bn] = 1.0f / fmaxf(sqrtf(s), 1e-12f);
    }
}

// ---------------- diversity ----------------
__global__ void div_s_kernel(const float* __restrict__ attn, const float* __restrict__ invn)
{
    __shared__ float sinv[304];
    __shared__ float red[256];
    int b = blockIdx.y, t = threadIdx.x;
    for (int i = t; i < NN; i += 256) sinv[i] = invn[b * NN + i];
    __syncthreads();
    int m = blockIdx.x * 256 + t;
    const float* base = attn + (long long)b * NN * MM + m;
    float s = 0.f;
    for (int n = 0; n < NN; n++) s += base[(long long)n * MM] * sinv[n];
    red[t] = s * s; __syncthreads();
    for (int k = 128; k > 0; k >>= 1) { if (t < k) red[t] += red[t + k]; __syncthreads(); }
    if (t == 0) g_divpart[b * 16 + blockIdx.x] = red[0];
}

__global__ void finalize_div(float* __restrict__ outdiv)
{
    __shared__ float red[256];
    int t = threadIdx.x;
    red[t] = g_divpart[t]; __syncthreads();
    for (int k = 128; k > 0; k >>= 1) { if (t < k) red[t] += red[t + k]; __syncthreads(); }
    if (t == 0) outdiv[0] = (red[0] - (float)(BB * NN)) * (0.1f / ((float)NN * (NN - 1)));
}

// ---------------- LayerNorm(256) + ReLU (tf32 out), shuffle reductions ----------------
__global__ void __launch_bounds__(256) ln_relu_kernel(
    float* __restrict__ z, const float* __restrict__ g, const float* __restrict__ bb)
{
    __shared__ float red[8];
    __shared__ float bc;
    int row = blockIdx.x, t = threadIdx.x, lane = t & 31, wid = t >> 5;
    float v = z[(long long)row * 256 + t];
    float s = v;
#pragma unroll
    for (int st = 16; st > 0; st >>= 1) s += __shfl_xor_sync(0xFFFFFFFFu, s, st);
    if (lane == 0) red[wid] = s;
    __syncthreads();
    if (t == 0) { float a = 0.f; for (int i = 0; i < 8; i++) a += red[i]; bc = a * (1.f / 256.f); }
    __syncthreads();
    float mu = bc;
    float d = v - mu;
    s = d * d;
#pragma unroll
    for (int st = 16; st > 0; st >>= 1) s += __shfl_xor_sync(0xFFFFFFFFu, s, st);
    __syncthreads();
    if (lane == 0) red[wid] = s;
    __syncthreads();
    if (t == 0) { float a = 0.f; for (int i = 0; i < 8; i++) a += red[i]; bc = a * (1.f / 256.f); }
    __syncthreads();
    float var = bc;
    float o = d * rsqrtf(var + 1e-5f) * g[t] + bb[t];
    z[(long long)row * 256 + t] = tf32_rna(fmaxf(o, 0.f));
}

// ---------------- SIMT GEMM NT (small finals) ----------------
template<int EPI>
__global__ void __launch_bounds__(256) gemm_nt(
    const float* __restrict__ Ab, const float* __restrict__ Bb, float* __restrict__ Cb,
    int I, int J, int K, const float* __restrict__ bias)
{
    __shared__ float As[BK][TILE + 4];
    __shared__ float Bs[BK][TILE + 4];
    int t = threadIdx.x, tx = t & 15, ty = t >> 4;
    int iB = blockIdx.y * TILE, jB = blockIdx.x * TILE;

    float acc[8][8];
#pragma unroll
    for (int i = 0; i < 8; i++)
#pragma unroll
        for (int j = 0; j < 8; j++) acc[i][j] = 0.f;

    for (int k0 = 0; k0 < K; k0 += BK) {
#pragma unroll
        for (int r = 0; r < 2; r++) {
            int idx = t + r * 256;
            int row = idx >> 2, kq = (idx & 3) * 4;
            float4 v = make_float4(0.f, 0.f, 0.f, 0.f);
            int i = iB + row;
            if (i < I) v = *(const float4*)(Ab + (long long)i * K + k0 + kq);
            As[kq + 0][row] = v.x; As[kq + 1][row] = v.y;
            As[kq + 2][row] = v.z; As[kq + 3][row] = v.w;
        }
#pragma unroll
        for (int r = 0; r < 2; r++) {
            int idx = t + r * 256;
            int row = idx >> 2, kq = (idx & 3) * 4;
            float4 v = make_float4(0.f, 0.f, 0.f, 0.f);
            int j = jB + row;
            if (j < J) v = *(const float4*)(Bb + (long long)j * K + k0 + kq);
            Bs[kq + 0][row] = v.x; Bs[kq + 1][row] = v.y;
            Bs[kq + 2][row] = v.z; Bs[kq + 3][row] = v.w;
        }
        __syncthreads();
#pragma unroll
        for (int k = 0; k < BK; k++) {
            float a[8], bv[8];
            *(float4*)&a[0]  = *(const float4*)&As[k][ty * 4];
            *(float4*)&a[4]  = *(const float4*)&As[k][ty * 4 + 64];
            *(float4*)&bv[0] = *(const float4*)&Bs[k][tx * 4];
            *(float4*)&bv[4] = *(const float4*)&Bs[k][tx * 4 + 64];
#pragma unroll
            for (int i = 0; i < 8; i++)
#pragma unroll
                for (int j = 0; j < 8; j++) acc[i][j] += a[i] * bv[j];
        }
        __syncthreads();
    }
#pragma unroll
    for (int i = 0; i < 8; i++) {
        int ii = iB + (i < 4 ? ty * 4 + i : 64 + ty * 4 + i - 4);
        if (ii >= I) continue;
#pragma unroll
        for (int j = 0; j < 8; j++) {
            int jj = jB + (j < 4 ? tx * 4 + j : 64 + tx * 4 + j - 4);
            if (jj >= J) continue;
            float v = acc[i][j];
            if (bias) v += bias[jj];
            if (EPI == 1) v = fmaxf(v, 0.f);
            else if (EPI == 2) v = 1.0f / (1.0f + __expf(-v));
            Cb[(long long)ii * J + jj] = v;
        }
    }
}

// ================= sf = attn @ vals^T — 64n x 64c tiles, occupancy 2 =================
#define SF_SMEM (2 * (64 + 64) * 36 * 4)   // 36864

__global__ void __launch_bounds__(256, 2) sf_hmma_kernel(
    const float* __restrict__ attn_t, const float* __restrict__ vals,
    float* __restrict__ sfb, float* __restrict__ outsf)
{
    extern __shared__ float smf[];
    float* As = smf;                    // [2][64*36]
    float* Bs = smf + 2 * 64 * 36;      // [2][64*36]
    int t = threadIdx.x;
    int lane = t & 31, w = t >> 5;
    int wn0 = (w & 1) * 32, wc0 = (w >> 1) * 16;
    int g = lane >> 2, tq = lane & 3;
    int n0 = blockIdx.y * 64, c0 = blockIdx.x * 64, b = blockIdx.z;

    int col4 = (t & 7) * 4;
    int row0 = t >> 3;                  // 0..31

    const float* Ab = attn_t + (long long)b * NN * MM;
    const float* Bb = vals + (long long)b * HID * MM;

    float acc[2][2][4];
#pragma unroll
    for (int mi = 0; mi < 2; mi++)
#pragma unroll
        for (int ni = 0; ni < 2; ni++)
#pragma unroll
            for (int r = 0; r < 4; r++) acc[mi][ni][r] = 0.f;

    float4 ra[2], rb[2];
#pragma unroll
    for (int i = 0; i < 2; i++) {
        int r = row0 + 32 * i;
        int an = n0 + r; if (an > NN - 1) an = NN - 1;
        ra[i] = *(const float4*)(Ab + (long long)an * MM + col4);
        rb[i] = *(const float4*)(Bb + (long long)(c0 + r) * MM + col4);
    }
#pragma unroll
    for (int i = 0; i < 2; i++) {
        int r = row0 + 32 * i;
        *(float4*)&As[r * 36 + col4] = ra[i];
        *(float4*)&Bs[r * 36 + col4] = rb[i];
    }
    __syncthreads();

    for (int ch = 0; ch < MM / 32; ch++) {
        int buf = ch & 1;
        bool more = (ch + 1) < MM / 32;
        if (more) {
            int k0 = (ch + 1) * 32 + col4;
#pragma unroll
            for (int i = 0; i < 2; i++) {
                int r = row0 + 32 * i;
                int an = n0 + r; if (an > NN - 1) an = NN - 1;
                ra[i] = *(const float4*)(Ab + (long long)an * MM + k0);
                rb[i] = *(const float4*)(Bb + (long long)(c0 + r) * MM + k0);
            }
        }
        const uint32_t* Asu = (const uint32_t*)(As + buf * 64 * 36);
        const uint32_t* Bsu = (const uint32_t*)(Bs + buf * 64 * 36);
#pragma unroll
        for (int ks = 0; ks < 4; ks++) {
            int kk = ks * 8 + tq;
            uint32_t a[2][4];
#pragma unroll
            for (int mi = 0; mi < 2; mi++) {
                int r = wn0 + 16 * mi + g;
                a[mi][0] = Asu[r * 36 + kk];
                a[mi][1] = Asu[(r + 8) * 36 + kk];
                a[mi][2] = Asu[r * 36 + kk + 4];
                a[mi][3] = Asu[(r + 8) * 36 + kk + 4];
            }
            uint32_t bf[2][2];
#pragma unroll
            for (int ni = 0; ni < 2; ni++) {
                int c = wc0 + ni * 8 + g;
                bf[ni][0] = Bsu[c * 36 + kk];
                bf[ni][1] = Bsu[c * 36 + kk + 4];
            }
#pragma unroll
            for (int mi = 0; mi < 2; mi++)
#pragma unroll
                for (int ni = 0; ni < 2; ni++)
                    mma_tf32(acc[mi][ni], a[mi], bf[ni]);
        }
        if (more) {
            float* Ad = As + (buf ^ 1) * 64 * 36;
            float* Bd = Bs + (buf ^ 1) * 64 * 36;
#pragma unroll
            for (int i = 0; i < 2; i++) {
                int r = row0 + 32 * i;
                *(float4*)&Ad[r * 36 + col4] = ra[i];
                *(float4*)&Bd[r * 36 + col4] = rb[i];
            }
        }
        __syncthreads();
    }

#pragma unroll
    for (int mi = 0; mi < 2; mi++) {
#pragma unroll
        for (int ni = 0; ni < 2; ni++) {
            int c = c0 + wc0 + ni * 8 + 2 * tq;
#pragma unroll
            for (int hh = 0; hh < 2; hh++) {
                int n1 = n0 + wn0 + 16 * mi + g + 8 * hh;
                if (n1 < NN) {
                    long long o = ((long long)b * NN + n1) * HID + c;
                    float vx = acc[mi][ni][2 * hh], vy = acc[mi][ni][2 * hh + 1];
                    *(float2*)(sfb + o) = make_float2(tf32_rna(vx), tf32_rna(vy));
                    outsf[o] = vx; outsf[o + 1] = vy;
                }
            }
        }
    }
}

// ---------------- host ----------------
extern "C" void kernel_launch(void* const* d_in, const int* in_sizes, int n_in,
                              void* d_out_, int out_size)
{
    const float* x      = (const float*)d_in[0];
    const float* q      = (const float*)d_in[1];
    const float* pos_w  = (const float*)d_in[2];
    const float* pos_b  = (const float*)d_in[3];
    const float* fp_w   = (const float*)d_in[4];
    const float* fp_b   = (const float*)d_in[5];
    const float* bn_g   = (const float*)d_in[6];
    const float* bn_b   = (const float*)d_in[7];
    const float* bn_m   = (const float*)d_in[8];
    const float* bn_v   = (const float*)d_in[9];
    const float* key_w  = (const float*)d_in[10];
    const float* key_b  = (const float*)d_in[11];
    const float* val_w  = (const float*)d_in[12];
    const float* val_b  = (const float*)d_in[13];
    const float* ctp_w  = (const float*)d_in[14];
    const float* ctp_b  = (const float*)d_in[15];
    const float* bb1_w  = (const float*)d_in[16];
    const float* bb1_b  = (const float*)d_in[17];
    const float* bbln_g = (const float*)d_in[18];
    const float* bbln_b = (const float*)d_in[19];
    const float* bb2_w  = (const float*)d_in[20];
    const float* bb2_b  = (const float*)d_in[21];
    const float* bb3_w  = (const float*)d_in[22];
    const float* bb3_b  = (const float*)d_in[23];
    const float* ch1_w  = (const float*)d_in[24];
    const float* ch1_b  = (const float*)d_in[25];
    const float* chln_g = (const float*)d_in[26];
    const float* chln_b = (const float*)d_in[27];
    const float* ch2_w  = (const float*)d_in[28];
    const float* ch2_b  = (const float*)d_in[29];
    const float* ch3_w  = (const float*)d_in[30];
    const float* ch3_b  = (const float*)d_in[31];
    float* out = (float*)d_out_;

    float *ft, *kt, *vals, *pos, *posk, *poskt, *posv, *logits, *attn_t, *invn, *sfb,
          *h1, *h2, *bns, *bnt, *fpwt, *keywt, *valwt, *qt, *hbb1, *hch1, *hbb2, *hch2;
    cudaGetSymbolAddress((void**)&ft,     g_ft);
    cudaGetSymbolAddress((void**)&kt,     g_kt);
    cudaGetSymbolAddress((void**)&vals,   g_vals);
    cudaGetSymbolAddress((void**)&pos,    g_pos);
    cudaGetSymbolAddress((void**)&posk,   g_posk);
    cudaGetSymbolAddress((void**)&poskt,  g_poskt);
    cudaGetSymbolAddress((void**)&posv,   g_posv);
    cudaGetSymbolAddress((void**)&logits, g_logits);
    cudaGetSymbolAddress((void**)&attn_t, g_attn_t);
    cudaGetSymbolAddress((void**)&invn,   g_invn);
    cudaGetSymbolAddress((void**)&sfb,    g_sf);
    cudaGetSymbolAddress((void**)&h1,     g_h1);
    cudaGetSymbolAddress((void**)&h2,     g_h2);
    cudaGetSymbolAddress((void**)&bns,    g_bns);
    cudaGetSymbolAddress((void**)&bnt,    g_bnt);
    cudaGetSymbolAddress((void**)&fpwt,   g_fpwt);
    cudaGetSymbolAddress((void**)&keywt,  g_keywt);
    cudaGetSymbolAddress((void**)&valwt,  g_valwt);
    cudaGetSymbolAddress((void**)&qt,     g_qt);
    cudaGetSymbolAddress((void**)&hbb1,   g_hbb1);
    cudaGetSymbolAddress((void**)&hch1,   g_hch1);
    cudaGetSymbolAddress((void**)&hbb2,   g_hbb2);
    cudaGetSymbolAddress((void**)&hch2,   g_hch2);
    float* xt = logits;  // alias: xt consumed before logits written (stream-ordered)

    cudaFuncSetAttribute(sf_hmma_kernel, cudaFuncAttributeMaxDynamicSharedMemorySize, SF_SMEM);
    cudaFuncSetAttribute(hmma_nt_g<128, 0>, cudaFuncAttributeMaxDynamicSharedMemorySize, HS128);
    cudaFuncSetAttribute(hmma_nt_g<128, 1>, cudaFuncAttributeMaxDynamicSharedMemorySize, HS128);
    cudaFuncSetAttribute(hmma_nt_g<64, 1>,  cudaFuncAttributeMaxDynamicSharedMemorySize, HS64);
    cudaFuncSetAttribute(hmma_nt_g<128, 2>, cudaFuncAttributeMaxDynamicSharedMemorySize, HS128);
    cudaFuncSetAttribute(hmma_nt_g<128, 3>, cudaFuncAttributeMaxDynamicSharedMemorySize, HS128);

    // 1. BN fold + all tf32 weight rounds in one launch
    init_kernel<<<1, 128>>>(fp_b, bn_g, bn_b, bn_m, bn_v);
    RoundJobs rj;
    rj.j[0] = {fp_w,  fpwt,  128 * 256, 1.f};
    rj.j[1] = {key_w, keywt, 64 * 256,  1.f};
    rj.j[2] = {val_w, valwt, 256 * 256, 1.f};
    rj.j[3] = {q,     qt,    NN * 64,   0.25f};
    rj.j[4] = {bb1_w, hbb1,  256 * 256, 1.f};
    rj.j[5] = {ch1_w, hch1,  256 * 256, 1.f};
    rj.j[6] = {bb2_w, hbb2,  128 * 256, 1.f};
    rj.j[7] = {ch2_w, hch2,  128 * 256, 1.f};
    round_many<<<160, 256>>>(rj);
    // 2. positional channels + pos contributions
    pos_kernel<<<dim3(16, 128), 256>>>(pos_w, pos_b);
    gemm_nn_pos<<<dim3(32, 1, 1), 256>>>(key_w + 128, 256, pos, posk, 64, MM, 128, key_b);
    gemm_nn_pos<<<dim3(32, 2, 1), 256>>>(val_w + 128, 256, pos, posv, 256, MM, 128, val_b);
    transpose_kernel<false><<<dim3(128, 2, 1), dim3(32, 8)>>>(posk, poskt, 64, MM, 0, 0);
    // 3. x transpose (tf32-rounded)
    transpose_kernel<true><<<dim3(128, 8, BB), dim3(32, 8)>>>(x, xt, CC, MM,
                                                              (long long)CC * MM, (long long)MM * CC);
    // 4. ft = tf32(relu(bn(xt @ fp_w^T)))
    hmma_nt_g<128, 0><<<dim3(1, 32, BB), 256, HS128>>>(xt, fpwt, ft,
        MM, 256, 256, 256, 128, MM, (long long)MM * 256, 0, (long long)MM * 128,
        nullptr, bns, bnt);
    // 5. kt = tf32(ft @ key_w^T + poskt)
    hmma_nt_g<64, 1><<<dim3(1, 32, BB), 256, HS64>>>(ft, keywt, kt,
        MM, 128, 128, 256, 64, MM, (long long)MM * 128, 0, (long long)MM * 64,
        poskt, nullptr, nullptr);
    // 6. vals = tf32(val_w @ ft^T + posv)
    hmma_nt_g<128, 1><<<dim3(32, 2, BB), 256, HS128>>>(valwt, ft, vals,
        256, 128, 256, 128, MM, 256, 0, (long long)MM * 128, (long long)MM * 256,
        posv, nullptr, nullptr);
    // 7. logits
    logits_hmma<<<dim3(32, 3, BB * 4), 256>>>(qt, kt, logits);
    // 8. softmax (register-resident)
    softmax_kernel<<<BB * NN, 256>>>(logits, out + OFF_MAPS, attn_t, invn);
    // 9. diversity
    div_s_kernel<<<dim3(16, BB), 256>>>(out + OFF_MAPS, invn);
    finalize_div<<<1, 256>>>(out + OFF_DIV);
    // 10. sf = attn @ vals^T  (64x64 tiles, 320 blocks)
    sf_hmma_kernel<<<dim3(4, 5, BB), 256, SF_SMEM>>>(attn_t, vals, sfb, out + OFF_SF);
    // 11. box head (HMMA first two layers)
    hmma_nt_g<128, 2><<<dim3(2, 38, 1), 256, HS128>>>(sfb, hbb1, h1,
        BB * NN, 256, 256, 256, 256, BB * NN, 0, 0, 0, nullptr, bb1_b, nullptr);
    ln_relu_kernel<<<BB * NN, 256>>>(h1, bbln_g, bbln_b);
    hmma_nt_g<128, 3><<<dim3(1, 38, 1), 256, HS128>>>(h1, hbb2, h2,
        BB * NN, 256, 256, 256, 128, BB * NN, 0, 0, 0, nullptr, bb2_b, nullptr);
    gemm_nt<0><<<dim3(1, 38, 1), 256>>>(h2, bb3_w, out + OFF_BOXES, BB * NN, 4, 128, bb3_b);
    // 12. score head
    hmma_nt_g<128, 2><<<dim3(2, 38, 1), 256, HS128>>>(sfb, hch1, h1,
        BB * NN, 256, 256, 256, 256, BB * NN, 0, 0, 0, nullptr, ch1_b, nullptr);
    ln_relu_kernel<<<BB * NN, 256>>>(h1, chln_g, chln_b);
    hmma_nt_g<128, 3><<<dim3(1, 38, 1), 256, HS128>>>(h1, hch2, h2,
        BB * NN, 256, 256, 256, 128, BB * NN, 0, 0, 0, nullptr, ch2_b, nullptr);
    gemm_nt<2><<<dim3(1, 38, 1), 256>>>(h2, ch3_w, out + OFF_SCORES, BB * NN, 1, 128, ch3_b);
    // 13. class head
    gemm_nt<0><<<dim3(1, 38, 1), 256>>>(sfb, ctp_w, out + OFF_CLS, BB * NN, NCC, 256, ctp_b);
}

// round 8
// speedup vs baseline: 1.8586x; 1.2026x over previous
#include <cuda_runtime.h>
#include <cstdint>
#include <math.h>

// ---------------- problem constants ----------------
#define BB   16
#define CC   256
#define MM   4096          // H*W
#define HID  256
#define NN   300
#define NCC  80

// output layout (flattened tuple: boxes, scores, cls, maps, div, sf)
#define OFF_BOXES  0LL
#define OFF_SCORES 19200LL
#define OFF_CLS    24000LL
#define OFF_MAPS   408000LL
#define OFF_DIV    20068800LL
#define OFF_SF     20068801LL

// ---------------- device scratch ----------------
__device__ float g_ft   [BB * 128 * MM];            // feats transposed [b][m][128], tf32
__device__ float g_kt   [BB * 64 * MM];             // keys transposed [b][m][64], tf32
__device__ float g_vals [BB * 256 * MM];            // vals [b][c][m], tf32
__device__ float g_poskt[MM * 64];                  // pos part of keys, [m][o]
__device__ float g_posv [256 * MM];                 // pos part of vals, [c][m]
__device__ float g_logits[(long long)BB * 4 * NN * MM];
__device__ float g_attn_t[(long long)BB * NN * MM]; // tf32-rounded attn
__device__ float g_invn [BB * NN];
__device__ float g_sf   [BB * NN * HID];            // tf32-rounded sf for heads
__device__ float g_h1   [2 * BB * NN * 256];        // [bb, ch]
__device__ float g_h2   [2 * BB * NN * 128];
__device__ float g_bns  [128];
__device__ float g_bnt  [128];
__device__ float g_divpart[256];
__device__ float g_fpwt [128 * 256];                // tf32 weight copies
__device__ float g_keywt[64 * 256];
__device__ float g_valwt[256 * 256];
__device__ float g_qt   [NN * 64];
__device__ float g_hw1  [2 * 256 * 256];            // [bb1, ch1] rounded
__device__ float g_hw2  [2 * 128 * 256];            // [bb2, ch2] rounded
__device__ float g_pra  [320];                      // pos rank-2: Ay (64 key + 256 val)
__device__ float g_prb  [320];                      // Ax
__device__ float g_prc  [320];                      // C (incl. bias)

__device__ __forceinline__ float tf32_rna(float v) {
    uint32_t u;
    asm("cvt.rna.tf32.f32 %0, %1;" : "=r"(u) : "f"(v));
    return __uint_as_float(u);
}
__device__ __forceinline__ void mma_tf32(float c[4], const uint32_t a[4], const uint32_t b[2]) {
    asm volatile(
        "mma.sync.aligned.m16n8k8.row.col.f32.tf32.tf32.f32 "
        "{%0,%1,%2,%3}, {%4,%5,%6,%7}, {%8,%9}, {%0,%1,%2,%3};"
        : "+f"(c[0]), "+f"(c[1]), "+f"(c[2]), "+f"(c[3])
        : "r"(a[0]), "r"(a[1]), "r"(a[2]), "r"(a[3]), "r"(b[0]), "r"(b[1]));
}
__device__ __forceinline__ float grid_y(int m) { return -1.0f + 2.0f * (float)(m >> 6) / 63.0f; }
__device__ __forceinline__ float grid_x(int m) { return -1.0f + 2.0f * (float)(m & 63) / 63.0f; }

// ---------------- small kernels ----------------
__global__ void init_kernel(const float* __restrict__ fp_b, const float* __restrict__ bn_g,
                            const float* __restrict__ bn_b, const float* __restrict__ bn_m,
                            const float* __restrict__ bn_v) {
    int t = threadIdx.x;
    if (t < 128) {
        float s = bn_g[t] * rsqrtf(bn_v[t] + 1e-5f);
        g_bns[t] = s;
        g_bnt[t] = (fp_b[t] - bn_m[t]) * s + bn_b[t];
    }
}

struct RoundJob { const float* s; float* d; int n; float sc; };
struct RoundJobs { RoundJob j[8]; };
__global__ void round_many(RoundJobs jobs) {
    int tid = blockIdx.x * 256 + threadIdx.x;
    int stride = gridDim.x * 256;
#pragma unroll
    for (int k = 0; k < 8; k++) {
        const RoundJob J = jobs.j[k];
        for (int i = tid; i < J.n; i += stride) J.d[i] = tf32_rna(J.s[i] * J.sc);
    }
}

// pos rank-2 reduce
__global__ void pos_reduce_kernel(const float* __restrict__ key_w, const float* __restrict__ val_w,
                                  const float* __restrict__ pos_w, const float* __restrict__ pos_b,
                                  const float* __restrict__ key_b, const float* __restrict__ val_b)
{
    int idx = blockIdx.x * 256 + threadIdx.x;   // 0..959
    if (idx >= 960) return;
    int which = idx % 3;
    int oa = idx / 3;
    const float* w;
    float bias;
    if (oa < 64) { w = key_w + oa * 256 + 128; bias = key_b[oa]; }
    else         { w = val_w + (oa - 64) * 256 + 128; bias = val_b[oa - 64]; }
    float s = 0.f;
    for (int c = 0; c < 128; c++) {
        float p = (which == 0) ? pos_w[2 * c] : (which == 1) ? pos_w[2 * c + 1] : pos_b[c];
        s += w[c] * p;
    }
    if (which == 0) g_pra[oa] = s;
    else if (which == 1) g_prb[oa] = s;
    else g_prc[oa] = s + bias;
}

// evaluate poskt[m][64] and posv[256][m] elementwise
__global__ void pos_eval_kernel() {
    int bid = blockIdx.x;
    int t = threadIdx.x;
    if (bid < 1024) {          // poskt: 64*4096 elems, [m][o]
        int idx = bid * 256 + t;
        int o = idx & 63, m = idx >> 6;
        g_poskt[idx] = g_pra[o] * grid_y(m) + g_prb[o] * grid_x(m) + g_prc[o];
    } else {                   // posv: 256*4096 elems, [c][m]
        int idx = (bid - 1024) * 256 + t;
        int m = idx & (MM - 1), c = idx >> 12;
        g_posv[idx] = g_pra[64 + c] * grid_y(m) + g_prb[64 + c] * grid_x(m) + g_prc[64 + c];
    }
}

// ================= ft HMMA with fused transpose =================
#define FT_SMEM ((2 * 32 * 136 + 2 * 128 * 36) * 4)   // 71680 B

__global__ void __launch_bounds__(256, 1) ft_hmma(
    const float* __restrict__ xg, const float* __restrict__ Bw, float* __restrict__ Cb,
    const float* __restrict__ e1, const float* __restrict__ e2)
{
    extern __shared__ float smf[];
    float* As = smf;                    // [2][32][136]
    float* Bs = smf + 2 * 32 * 136;     // [2][128*36]
    int t = threadIdx.x, lane = t & 31, w = t >> 5;
    int wn0 = (w & 3) * 32, wc0 = (w >> 2) * 64;
    int g = lane >> 2, tq = lane & 3;
    int i0 = blockIdx.y * 128, b = blockIdx.z;
    const float* A = xg + (long long)b * CC * MM;
    float* C = Cb + (long long)b * MM * 128;
    int col4 = (t & 7) * 4, row0 = t >> 3;
    int am4 = (t & 31) * 4, ac0 = t >> 5;

    float acc[2][8][4];
#pragma unroll
    for (int mi = 0; mi < 2; mi++)
#pragma unroll
        for (int ni = 0; ni < 8; ni++)
#pragma unroll
            for (int r = 0; r < 4; r++) acc[mi][ni][r] = 0.f;

    float4 ra[4], rb[4];
#pragma unroll
    for (int i = 0; i < 4; i++) {
        int c = ac0 + 8 * i;
        ra[i] = *(const float4*)(A + (long long)c * MM + i0 + am4);
        rb[i] = *(const float4*)(Bw + (long long)(row0 + 32 * i) * 256 + col4);
    }
#pragma unroll
    for (int i = 0; i < 4; i++) {
        int c = ac0 + 8 * i;
        float4 v = ra[i];
        v.x = tf32_rna(v.x); v.y = tf32_rna(v.y); v.z = tf32_rna(v.z); v.w = tf32_rna(v.w);
        *(float4*)&As[c * 136 + am4] = v;
        *(float4*)&Bs[(row0 + 32 * i) * 36 + col4] = rb[i];
    }
    __syncthreads();

    for (int ch = 0; ch < 8; ch++) {
        int buf = ch & 1;
        bool more = (ch + 1) < 8;
        if (more) {
            int k0 = (ch + 1) * 32;
#pragma unroll
            for (int i = 0; i < 4; i++) {
                int c = k0 + ac0 + 8 * i;
                ra[i] = *(const float4*)(A + (long long)c * MM + i0 + am4);
                rb[i] = *(const float4*)(Bw + (long long)(row0 + 32 * i) * 256 + k0 + col4);
            }
        }
        const uint32_t* Asu = (const uint32_t*)(As + buf * 32 * 136);
        const uint32_t* Bsu = (const uint32_t*)(Bs + buf * 128 * 36);
#pragma unroll
        for (int ks = 0; ks < 4; ks++) {
            int kk = ks * 8 + tq;
            uint32_t a[2][4];
#pragma unroll
            for (int mi = 0; mi < 2; mi++) {
                int r = wn0 + 16 * mi + g;
                a[mi][0] = Asu[kk * 136 + r];
                a[mi][1] = Asu[kk * 136 + r + 8];
                a[mi][2] = Asu[(kk + 4) * 136 + r];
                a[mi][3] = Asu[(kk + 4) * 136 + r + 8];
            }
            uint32_t bf[8][2];
#pragma unroll
            for (int ni = 0; ni < 8; ni++) {
                int c = wc0 + ni * 8 + g;
                bf[ni][0] = Bsu[c * 36 + kk];
                bf[ni][1] = Bsu[c * 36 + kk + 4];
            }
#pragma unroll
            for (int mi = 0; mi < 2; mi++)
#pragma unroll
                for (int ni = 0; ni < 8; ni++)
                    mma_tf32(acc[mi][ni], a[mi], bf[ni]);
        }
        if (more) {
            float* Ad = As + (buf ^ 1) * 32 * 136;
            float* Bd = Bs + (buf ^ 1) * 128 * 36;
#pragma unroll
            for (int i = 0; i < 4; i++) {
                int c = ac0 + 8 * i;
                float4 v = ra[i];
                v.x = tf32_rna(v.x); v.y = tf32_rna(v.y); v.z = tf32_rna(v.z); v.w = tf32_rna(v.w);
                *(float4*)&Ad[c * 136 + am4] = v;
                *(float4*)&Bd[(row0 + 32 * i) * 36 + col4] = rb[i];
            }
        }
        __syncthreads();
    }

#pragma unroll
    for (int mi = 0; mi < 2; mi++) {
#pragma unroll
        for (int ni = 0; ni < 8; ni++) {
            int jg = wc0 + ni * 8 + 2 * tq;
#pragma unroll
            for (int hh = 0; hh < 2; hh++) {
                int i = i0 + wn0 + 16 * mi + g + 8 * hh;
                float v0 = tf32_rna(fmaxf(acc[mi][ni][2 * hh] * e1[jg] + e2[jg], 0.f));
                float v1 = tf32_rna(fmaxf(acc[mi][ni][2 * hh + 1] * e1[jg + 1] + e2[jg + 1], 0.f));
                *(float2*)(C + (long long)i * 128 + jg) = make_float2(v0, v1);
            }
        }
    }
}

// ================= generic NT HMMA tf32 =================
// EPI 1: tf32(acc+C0)  EPI 2: acc+bias[j]  EPI 3: relu(acc+bias[j]); bias z-selected via e1z
#define HS128 73728
#define HS64  55296

template<int NJ, int EPI>
__global__ void __launch_bounds__(256, 1) hmma_nt_g(
    const float* __restrict__ Ab, const float* __restrict__ Bb, float* __restrict__ Cb,
    int I, int K, int lda, int ldb, int ldc, int clampI,
    long long az, long long bz, long long cz,
    const float* __restrict__ C0, const float* __restrict__ e1, const float* __restrict__ e1z)
{
    extern __shared__ float smf[];
    const int NI_ACC = NJ / 16;
    const int NB = NJ / 32;
    float* As = smf;
    float* Bs = smf + 2 * 128 * 36;
    int t = threadIdx.x, lane = t & 31, w = t >> 5;
    int wn0 = (w & 3) * 32, wc0 = (w >> 2) * (NJ / 2);
    int g = lane >> 2, tq = lane & 3;
    int j0 = blockIdx.x * NJ, i0 = blockIdx.y * 128, b = blockIdx.z;
    const float* A = Ab + az * b;
    const float* B = Bb + bz * b;
    float* C = Cb + cz * b;
    int col4 = (t & 7) * 4, row0 = t >> 3;

    float acc[2][NI_ACC][4];
#pragma unroll
    for (int mi = 0; mi < 2; mi++)
#pragma unroll
        for (int ni = 0; ni < NI_ACC; ni++)
#pragma unroll
            for (int r = 0; r < 4; r++) acc[mi][ni][r] = 0.f;

    float4 ra[4], rb[NB];
#pragma unroll
    for (int i = 0; i < 4; i++) {
        int r = row0 + 32 * i;
        int ar = i0 + r; ar = ar < clampI ? ar : clampI - 1;
        ra[i] = *(const float4*)(A + (long long)ar * lda + col4);
    }
#pragma unroll
    for (int i = 0; i < NB; i++) {
        int r = row0 + 32 * i;
        rb[i] = *(const float4*)(B + (long long)(j0 + r) * ldb + col4);
    }
#pragma unroll
    for (int i = 0; i < 4; i++) { int r = row0 + 32 * i; *(float4*)&As[r * 36 + col4] = ra[i]; }
#pragma unroll
    for (int i = 0; i < NB; i++) { int r = row0 + 32 * i; *(float4*)&Bs[r * 36 + col4] = rb[i]; }
    __syncthreads();

    int nch = K / 32;
    for (int ch = 0; ch < nch; ch++) {
        int buf = ch & 1;
        bool more = (ch + 1) < nch;
        if (more) {
            int k0 = (ch + 1) * 32 + col4;
#pragma unroll
            for (int i = 0; i < 4; i++) {
                int r = row0 + 32 * i;
                int ar = i0 + r; ar = ar < clampI ? ar : clampI - 1;
                ra[i] = *(const float4*)(A + (long long)ar * lda + k0);
            }
#pragma unroll
            for (int i = 0; i < NB; i++) {
                int r = row0 + 32 * i;
                rb[i] = *(const float4*)(B + (long long)(j0 + r) * ldb + k0);
            }
        }
        const uint32_t* Asu = (const uint32_t*)(As + buf * 128 * 36);
        const uint32_t* Bsu = (const uint32_t*)(Bs + buf * NJ * 36);
#pragma unroll
        for (int ks = 0; ks < 4; ks++) {
            int kk = ks * 8 + tq;
            uint32_t a[2][4];
#pragma unroll
            for (int mi = 0; mi < 2; mi++) {
                int r = wn0 + 16 * mi + g;
                a[mi][0] = Asu[r * 36 + kk];
                a[mi][1] = Asu[(r + 8) * 36 + kk];
                a[mi][2] = Asu[r * 36 + kk + 4];
                a[mi][3] = Asu[(r + 8) * 36 + kk + 4];
            }
            uint32_t bf[NI_ACC][2];
#pragma unroll
            for (int ni = 0; ni < NI_ACC; ni++) {
                int c = wc0 + ni * 8 + g;
                bf[ni][0] = Bsu[c * 36 + kk];
                bf[ni][1] = Bsu[c * 36 + kk + 4];
            }
#pragma unroll
            for (int mi = 0; mi < 2; mi++)
#pragma unroll
                for (int ni = 0; ni < NI_ACC; ni++)
                    mma_tf32(acc[mi][ni], a[mi], bf[ni]);
        }
        if (more) {
            float* Ad = As + (buf ^ 1) * 128 * 36;
            float* Bd = Bs + (buf ^ 1) * NJ * 36;
#pragma unroll
            for (int i = 0; i < 4; i++) { int r = row0 + 32 * i; *(float4*)&Ad[r * 36 + col4] = ra[i]; }
#pragma unroll
            for (int i = 0; i < NB; i++) { int r = row0 + 32 * i; *(float4*)&Bd[r * 36 + col4] = rb[i]; }
        }
        __syncthreads();
    }

    const float* bp = (EPI >= 2 && b != 0 && e1z != nullptr) ? e1z : e1;
#pragma unroll
    for (int mi = 0; mi < 2; mi++) {
#pragma unroll
        for (int ni = 0; ni < NI_ACC; ni++) {
            int jg = j0 + wc0 + ni * 8 + 2 * tq;
#pragma unroll
            for (int hh = 0; hh < 2; hh++) {
                int i = i0 + wn0 + 16 * mi + g + 8 * hh;
                if (i >= I) continue;
                float v0 = acc[mi][ni][2 * hh], v1 = acc[mi][ni][2 * hh + 1];
                if (EPI == 1) {
                    long long ci = (long long)i * ldc + jg;
                    v0 = tf32_rna(v0 + C0[ci]);
                    v1 = tf32_rna(v1 + C0[ci + 1]);
                } else if (EPI == 2) {
                    v0 = v0 + bp[jg]; v1 = v1 + bp[jg + 1];
                } else if (EPI == 3) {
                    v0 = fmaxf(v0 + bp[jg], 0.f); v1 = fmaxf(v1 + bp[jg + 1], 0.f);
                }
                *(float2*)(C + (long long)i * ldc + jg) = make_float2(v0, v1);
            }
        }
    }
}

// ================= logits HMMA (K=16) =================
__global__ void __launch_bounds__(256) logits_hmma(
    const float* __restrict__ qt, const float* __restrict__ kt, float* __restrict__ logits)
{
    __shared__ float As[128 * 20], Bs[128 * 20];
    int t = threadIdx.x, lane = t & 31, w = t >> 5;
    int wn0 = (w & 3) * 32, wc0 = (w >> 2) * 64;
    int g = lane >> 2, tq = lane & 3;
    int m0 = blockIdx.x * 128, n0 = blockIdx.y * 128;
    int z = blockIdx.z, b = z >> 2, h = z & 3;
    const float* Aq = qt + h * 16;
    const float* Bk = kt + (long long)b * MM * 64 + h * 16;
#pragma unroll
    for (int i = 0; i < 2; i++) {
        int gi = t + i * 256;
        int row = gi >> 2, gc = (gi & 3) * 4;
        int nr = n0 + row; nr = nr < NN ? nr : NN - 1;
        *(float4*)&As[row * 20 + gc] = *(const float4*)(Aq + (long long)nr * 64 + gc);
        *(float4*)&Bs[row * 20 + gc] = *(const float4*)(Bk + (long long)(m0 + row) * 64 + gc);
    }
    __syncthreads();
    float acc[2][8][4];
#pragma unroll
    for (int mi = 0; mi < 2; mi++)
#pragma unroll
        for (int ni = 0; ni < 8; ni++)
#pragma unroll
            for (int r = 0; r < 4; r++) acc[mi][ni][r] = 0.f;
    const uint32_t* Asu = (const uint32_t*)As;
    const uint32_t* Bsu = (const uint32_t*)Bs;
#pragma unroll
    for (int ks = 0; ks < 2; ks++) {
        int kk = ks * 8 + tq;
        uint32_t a[2][4];
#pragma unroll
        for (int mi = 0; mi < 2; mi++) {
            int r = wn0 + 16 * mi + g;
            a[mi][0] = Asu[r * 20 + kk];
            a[mi][1] = Asu[(r + 8) * 20 + kk];
            a[mi][2] = Asu[r * 20 + kk + 4];
            a[mi][3] = Asu[(r + 8) * 20 + kk + 4];
        }
        uint32_t bf[8][2];
#pragma unroll
        for (int ni = 0; ni < 8; ni++) {
            int c = wc0 + ni * 8 + g;
            bf[ni][0] = Bsu[c * 20 + kk];
            bf[ni][1] = Bsu[c * 20 + kk + 4];
        }
#pragma unroll
        for (int mi = 0; mi < 2; mi++)
#pragma unroll
            for (int ni = 0; ni < 8; ni++)
                mma_tf32(acc[mi][ni], a[mi], bf[ni]);
    }
    long long base = (long long)z * NN * MM;
#pragma unroll
    for (int mi = 0; mi < 2; mi++) {
#pragma unroll
        for (int ni = 0; ni < 8; ni++) {
            int m = m0 + wc0 + ni * 8 + 2 * tq;
#pragma unroll
            for (int hh = 0; hh < 2; hh++) {
                int n = n0 + wn0 + 16 * mi + g + 8 * hh;
                if (n < NN)
                    *(float2*)(logits + base + (long long)n * MM + m) =
                        make_float2(acc[mi][ni][2 * hh], acc[mi][ni][2 * hh + 1]);
            }
        }
    }
}

// ---------------- register-resident softmax ----------------
__global__ void __launch_bounds__(256) softmax_kernel(
    const float* __restrict__ logits,
    float* __restrict__ attn, float* __restrict__ attn_t,
    float* __restrict__ invn)
{
    __shared__ float red[40];
    int bn = blockIdx.x;
    int b = bn / NN, n = bn - b * NN;
    int t = threadIdx.x, lane = t & 31, wid = t >> 5;
    float v[4][16];
#pragma unroll
    for (int h = 0; h < 4; h++) {
        const float* src = logits + ((long long)(b * 4 + h) * NN + n) * MM;
#pragma unroll
        for (int k = 0; k < 16; k++) v[h][k] = src[t + 256 * k];
    }
    float lm[4];
#pragma unroll
    for (int h = 0; h < 4; h++) {
        float m = v[h][0];
#pragma unroll
        for (int k = 1; k < 16; k++) m = fmaxf(m, v[h][k]);
#pragma unroll
        for (int s = 16; s > 0; s >>= 1) m = fmaxf(m, __shfl_xor_sync(0xFFFFFFFFu, m, s));
        lm[h] = m;
    }
    if (lane == 0) {
#pragma unroll
        for (int h = 0; h < 4; h++) red[wid * 4 + h] = lm[h];
    }
    __syncthreads();
    if (t < 32) {
        float x = red[t];
        x = fmaxf(x, __shfl_xor_sync(0xFFFFFFFFu, x, 4));
        x = fmaxf(x, __shfl_xor_sync(0xFFFFFFFFu, x, 8));
        x = fmaxf(x, __shfl_xor_sync(0xFFFFFFFFu, x, 16));
        if (t < 4) red[32 + t] = x;
    }
    __syncthreads();
    float mx[4];
#pragma unroll
    for (int h = 0; h < 4; h++) mx[h] = red[32 + h];
    float ls[4];
#pragma unroll
    for (int h = 0; h < 4; h++) {
        float s = 0.f;
#pragma unroll
        for (int k = 0; k < 16; k++) {
            float e = __expf(v[h][k] - mx[h]);
            v[h][k] = e; s += e;
        }
#pragma unroll
        for (int st = 16; st > 0; st >>= 1) s += __shfl_xor_sync(0xFFFFFFFFu, s, st);
        ls[h] = s;
    }
    __syncthreads();
    if (lane == 0) {
#pragma unroll
        for (int h = 0; h < 4; h++) red[wid * 4 + h] = ls[h];
    }
    __syncthreads();
    if (t < 32) {
        float x = red[t];
        x += __shfl_xor_sync(0xFFFFFFFFu, x, 4);
        x += __shfl_xor_sync(0xFFFFFFFFu, x, 8);
        x += __shfl_xor_sync(0xFFFFFFFFu, x, 16);
        if (t < 4) red[36 + t] = 0.25f / x;
    }
    __syncthreads();
    float rs[4];
#pragma unroll
    for (int h = 0; h < 4; h++) rs[h] = red[36 + h];
    float ss = 0.f;
    float* dst  = attn + (long long)bn * MM;
    float* dstt = attn_t + (long long)bn * MM;
#pragma unroll
    for (int k = 0; k < 16; k++) {
        float a = v[0][k] * rs[0] + v[1][k] * rs[1] + v[2][k] * rs[2] + v[3][k] * rs[3];
        int m = t + 256 * k;
        dst[m] = a; dstt[m] = tf32_rna(a); ss += a * a;
    }
#pragma unroll
    for (int st = 16; st > 0; st >>= 1) ss += __shfl_xor_sync(0xFFFFFFFFu, ss, st);
    __syncthreads();
    if (lane == 0) red[wid] = ss;
    __syncthreads();
    if (t == 0) {
        float s = 0.f;
#pragma unroll
        for (int i = 0; i < 8; i++) s += red[i];
        invn[bn] = 1.0f / fmaxf(sqrtf(s), 1e-12f);
    }
}

// ---------------- diversity ----------------
__global__ void div_s_kernel(const float* __restrict__ attn, const float* __restrict__ invn)
{
    __shared__ float sinv[304];
    __shared__ float red[256];
    int b = blockIdx.y, t = threadIdx.x;
    for (int i = t; i < NN; i += 256) sinv[i] = invn[b * NN + i];
    __syncthreads();
    int m = blockIdx.x * 256 + t;
    const float* base = attn + (long long)b * NN * MM + m;
    float s = 0.f;
    for (int n = 0; n < NN; n++) s += base[(long long)n * MM] * sinv[n];
    red[t] = s * s; __syncthreads();
    for (int k = 128; k > 0; k >>= 1) { if (t < k) red[t] += red[t + k]; __syncthreads(); }
    if (t == 0) g_divpart[b * 16 + blockIdx.x] = red[0];
}

__global__ void finalize_div(float* __restrict__ outdiv)
{
    __shared__ float red[256];
    int t = threadIdx.x;
    red[t] = g_divpart[t]; __syncthreads();
    for (int k = 128; k > 0; k >>= 1) { if (t < k) red[t] += red[t + k]; __syncthreads(); }
    if (t == 0) outdiv[0] = (red[0] - (float)(BB * NN)) * (0.1f / ((float)NN * (NN - 1)));
}

// ---------------- batched LayerNorm(256) + ReLU (tf32 out) ----------------
__global__ void __launch_bounds__(256) ln_relu2_kernel(
    float* __restrict__ zb,
    const float* __restrict__ g0, const float* __restrict__ b0,
    const float* __restrict__ g1, const float* __restrict__ b1)
{
    __shared__ float red[8];
    __shared__ float bc;
    int row = blockIdx.x, sel = blockIdx.y;
    int t = threadIdx.x, lane = t & 31, wid = t >> 5;
    float* z = zb + (long long)sel * BB * NN * 256;
    const float* g = sel ? g1 : g0;
    const float* bb = sel ? b1 : b0;
    float v = z[(long long)row * 256 + t];
    float s = v;
#pragma unroll
    for (int st = 16; st > 0; st >>= 1) s += __shfl_xor_sync(0xFFFFFFFFu, s, st);
    if (lane == 0) red[wid] = s;
    __syncthreads();
    if (t == 0) { float a = 0.f; for (int i = 0; i < 8; i++) a += red[i]; bc = a * (1.f / 256.f); }
    __syncthreads();
    float mu = bc;
    float d = v - mu;
    s = d * d;
#pragma unroll
    for (int st = 16; st > 0; st >>= 1) s += __shfl_xor_sync(0xFFFFFFFFu, s, st);
    __syncthreads();
    if (lane == 0) red[wid] = s;
    __syncthreads();
    if (t == 0) { float a = 0.f; for (int i = 0; i < 8; i++) a += red[i]; bc = a * (1.f / 256.f); }
    __syncthreads();
    float var = bc;
    float o = d * rsqrtf(var + 1e-5f) * g[t] + bb[t];
    z[(long long)row * 256 + t] = tf32_rna(fmaxf(o, 0.f));
}

// ---------------- SIMT GEMM NT (small finals) ----------------
#define TILE 128
#define BK   16

template<int EPI>
__global__ void __launch_bounds__(256) gemm_nt(
    const float* __restrict__ Ab, const float* __restrict__ Bb, float* __restrict__ Cb,
    int I, int J, int K, const float* __restrict__ bias)
{
    __shared__ float As[BK][TILE + 4];
    __shared__ float Bs[BK][TILE + 4];
    int t = threadIdx.x, tx = t & 15, ty = t >> 4;
    int iB = blockIdx.y * TILE, jB = blockIdx.x * TILE;

    float acc[8][8];
#pragma unroll
    for (int i = 0; i < 8; i++)
#pragma unroll
        for (int j = 0; j < 8; j++) acc[i][j] = 0.f;

    for (int k0 = 0; k0 < K; k0 += BK) {
#pragma unroll
        for (int r = 0; r < 2; r++) {
            int idx = t + r * 256;
            int row = idx >> 2, kq = (idx & 3) * 4;
            float4 v = make_float4(0.f, 0.f, 0.f, 0.f);
            int i = iB + row;
            if (i < I) v = *(const float4*)(Ab + (long long)i * K + k0 + kq);
            As[kq + 0][row] = v.x; As[kq + 1][row] = v.y;
            As[kq + 2][row] = v.z; As[kq + 3][row] = v.w;
        }
#pragma unroll
        for (int r = 0; r < 2; r++) {
            int idx = t + r * 256;
            int row = idx >> 2, kq = (idx & 3) * 4;
            float4 v = make_float4(0.f, 0.f, 0.f, 0.f);
            int j = jB + row;
            if (j < J) v = *(const float4*)(Bb + (long long)j * K + k0 + kq);
            Bs[kq + 0][row] = v.x; Bs[kq + 1][row] = v.y;
            Bs[kq + 2][row] = v.z; Bs[kq + 3][row] = v.w;
        }
        __syncthreads();
#pragma unroll
        for (int k = 0; k < BK; k++) {
            float a[8], bv[8];
            *(float4*)&a[0]  = *(const float4*)&As[k][ty * 4];
            *(float4*)&a[4]  = *(const float4*)&As[k][ty * 4 + 64];
            *(float4*)&bv[0] = *(const float4*)&Bs[k][tx * 4];
            *(float4*)&bv[4] = *(const float4*)&Bs[k][tx * 4 + 64];
#pragma unroll
            for (int i = 0; i < 8; i++)
#pragma unroll
                for (int j = 0; j < 8; j++) acc[i][j] += a[i] * bv[j];
        }
        __syncthreads();
    }
#pragma unroll
    for (int i = 0; i < 8; i++) {
        int ii = iB + (i < 4 ? ty * 4 + i : 64 + ty * 4 + i - 4);
        if (ii >= I) continue;
#pragma unroll
        for (int j = 0; j < 8; j++) {
            int jj = jB + (j < 4 ? tx * 4 + j : 64 + tx * 4 + j - 4);
            if (jj >= J) continue;
            float v = acc[i][j];
            if (bias) v += bias[jj];
            if (EPI == 1) v = fmaxf(v, 0.f);
            else if (EPI == 2) v = 1.0f / (1.0f + __expf(-v));
            Cb[(long long)ii * J + jj] = v;
        }
    }
}

// ================= sf = attn @ vals^T — 64n x 128c tiles, warp 32x32, occ 2 =================
#define SF_SMEM ((2 * 64 * 36 + 2 * 128 * 36) * 4)   // 55296

__global__ void __launch_bounds__(256, 2) sf_hmma_kernel(
    const float* __restrict__ attn_t, const float* __restrict__ vals,
    float* __restrict__ sfb, float* __restrict__ outsf)
{
    extern __shared__ float smf[];
    float* As = smf;                    // [2][64*36]
    float* Bs = smf + 2 * 64 * 36;      // [2][128*36]
    int t = threadIdx.x;
    int lane = t & 31, w = t >> 5;
    int wn0 = (w & 1) * 32, wc0 = (w >> 1) * 32;
    int g = lane >> 2, tq = lane & 3;
    int n0 = blockIdx.y * 64, c0 = blockIdx.x * 128, b = blockIdx.z;

    int col4 = (t & 7) * 4;
    int row0 = t >> 3;                  // 0..31

    const float* Ab = attn_t + (long long)b * NN * MM;
    const float* Bb = vals + (long long)b * HID * MM;

    float acc[2][4][4];
#pragma unroll
    for (int mi = 0; mi < 2; mi++)
#pragma unroll
        for (int ni = 0; ni < 4; ni++)
#pragma unroll
            for (int r = 0; r < 4; r++) acc[mi][ni][r] = 0.f;

    float4 ra[2], rb[4];
#pragma unroll
    for (int i = 0; i < 2; i++) {
        int r = row0 + 32 * i;
        int an = n0 + r; if (an > NN - 1) an = NN - 1;
        ra[i] = *(const float4*)(Ab + (long long)an * MM + col4);
    }
#pragma unroll
    for (int i = 0; i < 4; i++) {
        int r = row0 + 32 * i;
        rb[i] = *(const float4*)(Bb + (long long)(c0 + r) * MM + col4);
    }
#pragma unroll
    for (int i = 0; i < 2; i++) { int r = row0 + 32 * i; *(float4*)&As[r * 36 + col4] = ra[i]; }
#pragma unroll
    for (int i = 0; i < 4; i++) { int r = row0 + 32 * i; *(float4*)&Bs[r * 36 + col4] = rb[i]; }
    __syncthreads();

    for (int ch = 0; ch < MM / 32; ch++) {
        int buf = ch & 1;
        bool more = (ch + 1) < MM / 32;
        if (more) {
            int k0 = (ch + 1) * 32 + col4;
#pragma unroll
            for (int i = 0; i < 2; i++) {
                int r = row0 + 32 * i;
                int an = n0 + r; if (an > NN - 1) an = NN - 1;
                ra[i] = *(const float4*)(Ab + (long long)an * MM + k0);
            }
#pragma unroll
            for (int i = 0; i < 4; i++) {
                int r = row0 + 32 * i;
                rb[i] = *(const float4*)(Bb + (long long)(c0 + r) * MM + k0);
            }
        }
        const uint32_t* Asu = (const uint32_t*)(As + buf * 64 * 36);
        const uint32_t* Bsu = (const uint32_t*)(Bs + buf * 128 * 36);
#pragma unroll
        for (int ks = 0; ks < 4; ks++) {
            int kk = ks * 8 + tq;
            uint32_t a[2][4];
#pragma unroll
            for (int mi = 0; mi < 2; mi++) {
                int r = wn0 + 16 * mi + g;
                a[mi][0] = Asu[r * 36 + kk];
                a[mi][1] = Asu[(r + 8) * 36 + kk];
                a[mi][2] = Asu[r * 36 + kk + 4];
                a[mi][3] = Asu[(r + 8) * 36 + kk + 4];
            }
            uint32_t bf[4][2];
#pragma unroll
            for (int ni = 0; ni < 4; ni++) {
                int c = wc0 + ni * 8 + g;
                bf[ni][0] = Bsu[c * 36 + kk];
                bf[ni][1] = Bsu[c * 36 + kk + 4];
            }
#pragma unroll
            for (int mi = 0; mi < 2; mi++)
#pragma unroll
                for (int ni = 0; ni < 4; ni++)
                    mma_tf32(acc[mi][ni], a[mi], bf[ni]);
        }
        if (more) {
            float* Ad = As + (buf ^ 1) * 64 * 36;
            float* Bd = Bs + (buf ^ 1) * 128 * 36;
#pragma unroll
            for (int i = 0; i < 2; i++) { int r = row0 + 32 * i; *(float4*)&Ad[r * 36 + col4] = ra[i]; }
#pragma unroll
            for (int i = 0; i < 4; i++) { int r = row0 + 32 * i; *(float4*)&Bd[r * 36 + col4] = rb[i]; }
        }
        __syncthreads();
    }

#pragma unroll
    for (int mi = 0; mi < 2; mi++) {
#pragma unroll
        for (int ni = 0; ni < 4; ni++) {
            int c = c0 + wc0 + ni * 8 + 2 * tq;
#pragma unroll
            for (int hh = 0; hh < 2; hh++) {
                int n1 = n0 + wn0 + 16 * mi + g + 8 * hh;
                if (n1 < NN) {
                    long long o = ((long long)b * NN + n1) * HID + c;
                    float vx = acc[mi][ni][2 * hh], vy = acc[mi][ni][2 * hh + 1];
                    *(float2*)(sfb + o) = make_float2(tf32_rna(vx), tf32_rna(vy));
                    outsf[o] = vx; outsf[o + 1] = vy;
                }
            }
        }
    }
}

// ---------------- host ----------------
extern "C" void kernel_launch(void* const* d_in, const int* in_sizes, int n_in,
                              void* d_out_, int out_size)
{
    const float* x      = (const float*)d_in[0];
    const float* q      = (const float*)d_in[1];
    const float* pos_w  = (const float*)d_in[2];
    const float* pos_b  = (const float*)d_in[3];
    const float* fp_w   = (const float*)d_in[4];
    const float* fp_b   = (const float*)d_in[5];
    const float* bn_g   = (const float*)d_in[6];
    const float* bn_b   = (const float*)d_in[7];
    const float* bn_m   = (const float*)d_in[8];
    const float* bn_v   = (const float*)d_in[9];
    const float* key_w  = (const float*)d_in[10];
    const float* key_b  = (const float*)d_in[11];
    const float* val_w  = (const float*)d_in[12];
    const float* val_b  = (const float*)d_in[13];
    const float* ctp_w  = (const float*)d_in[14];
    const float* ctp_b  = (const float*)d_in[15];
    const float* bb1_w  = (const float*)d_in[16];
    const float* bb1_b  = (const float*)d_in[17];
    const float* bbln_g = (const float*)d_in[18];
    const float* bbln_b = (const float*)d_in[19];
    const float* bb2_w  = (const float*)d_in[20];
    const float* bb2_b  = (const float*)d_in[21];
    const float* bb3_w  = (const float*)d_in[22];
    const float* bb3_b  = (const float*)d_in[23];
    const float* ch1_w  = (const float*)d_in[24];
    const float* ch1_b  = (const float*)d_in[25];
    const float* chln_g = (const float*)d_in[26];
    const float* chln_b = (const float*)d_in[27];
    const float* ch2_w  = (const float*)d_in[28];
    const float* ch2_b  = (const float*)d_in[29];
    const float* ch3_w  = (const float*)d_in[30];
    const float* ch3_b  = (const float*)d_in[31];
    float* out = (float*)d_out_;

    float *ft, *kt, *vals, *logits, *attn_t, *invn, *sfb, *h1, *h2, *bns, *bnt,
          *fpwt, *keywt, *valwt, *qt, *hw1, *hw2, *poskt, *posv;
    cudaGetSymbolAddress((void**)&ft,     g_ft);
    cudaGetSymbolAddress((void**)&kt,     g_kt);
    cudaGetSymbolAddress((void**)&vals,   g_vals);
    cudaGetSymbolAddress((void**)&poskt,  g_poskt);
    cudaGetSymbolAddress((void**)&posv,   g_posv);
    cudaGetSymbolAddress((void**)&logits, g_logits);
    cudaGetSymbolAddress((void**)&attn_t, g_attn_t);
    cudaGetSymbolAddress((void**)&invn,   g_invn);
    cudaGetSymbolAddress((void**)&sfb,    g_sf);
    cudaGetSymbolAddress((void**)&h1,     g_h1);
    cudaGetSymbolAddress((void**)&h2,     g_h2);
    cudaGetSymbolAddress((void**)&bns,    g_bns);
    cudaGetSymbolAddress((void**)&bnt,    g_bnt);
    cudaGetSymbolAddress((void**)&fpwt,   g_fpwt);
    cudaGetSymbolAddress((void**)&keywt,  g_keywt);
    cudaGetSymbolAddress((void**)&valwt,  g_valwt);
    cudaGetSymbolAddress((void**)&qt,     g_qt);
    cudaGetSymbolAddress((void**)&hw1,    g_hw1);
    cudaGetSymbolAddress((void**)&hw2,    g_hw2);

    cudaFuncSetAttribute(sf_hmma_kernel, cudaFuncAttributeMaxDynamicSharedMemorySize, SF_SMEM);
    cudaFuncSetAttribute(ft_hmma, cudaFuncAttributeMaxDynamicSharedMemorySize, FT_SMEM);
    cudaFuncSetAttribute(hmma_nt_g<128, 1>, cudaFuncAttributeMaxDynamicSharedMemorySize, HS128);
    cudaFuncSetAttribute(hmma_nt_g<64, 1>,  cudaFuncAttributeMaxDynamicSharedMemorySize, HS64);
    cudaFuncSetAttribute(hmma_nt_g<128, 2>, cudaFuncAttributeMaxDynamicSharedMemorySize, HS128);
    cudaFuncSetAttribute(hmma_nt_g<128, 3>, cudaFuncAttributeMaxDynamicSharedMemorySize, HS128);

    // 1. BN fold + all tf32 weight rounds in one launch
    init_kernel<<<1, 128>>>(fp_b, bn_g, bn_b, bn_m, bn_v);
    RoundJobs rj;
    rj.j[0] = {fp_w,  fpwt,        128 * 256, 1.f};
    rj.j[1] = {key_w, keywt,       64 * 256,  1.f};
    rj.j[2] = {val_w, valwt,       256 * 256, 1.f};
    rj.j[3] = {q,     qt,          NN * 64,   0.25f};
    rj.j[4] = {bb1_w, hw1,         256 * 256, 1.f};
    rj.j[5] = {ch1_w, hw1 + 65536, 256 * 256, 1.f};
    rj.j[6] = {bb2_w, hw2,         128 * 256, 1.f};
    rj.j[7] = {ch2_w, hw2 + 32768, 128 * 256, 1.f};
    round_many<<<160, 256>>>(rj);
    // 2. pos rank-2: reduce + eval
    pos_reduce_kernel<<<4, 256>>>(key_w, val_w, pos_w, pos_b, key_b, val_b);
    pos_eval_kernel<<<5120, 256>>>();
    // 3. ft = tf32(relu(bn(x^T @ fp_w^T))) — fused transpose
    ft_hmma<<<dim3(1, 32, BB), 256, FT_SMEM>>>(x, fpwt, ft, bns, bnt);
    // 4. kt = tf32(ft @ key_w^T + poskt)
    hmma_nt_g<64, 1><<<dim3(1, 32, BB), 256, HS64>>>(ft, keywt, kt,
        MM, 128, 128, 256, 64, MM, (long long)MM * 128, 0, (long long)MM * 64,
        poskt, nullptr, nullptr);
    // 5. vals = tf32(val_w @ ft^T + posv)
    hmma_nt_g<128, 1><<<dim3(32, 2, BB), 256, HS128>>>(valwt, ft, vals,
        256, 128, 256, 128, MM, 256, 0, (long long)MM * 128, (long long)MM * 256,
        posv, nullptr, nullptr);
    // 6. logits
    logits_hmma<<<dim3(32, 3, BB * 4), 256>>>(qt, kt, logits);
    // 7. softmax
    softmax_kernel<<<BB * NN, 256>>>(logits, out + OFF_MAPS, attn_t, invn);
    // 8. diversity
    div_s_kernel<<<dim3(16, BB), 256>>>(out + OFF_MAPS, invn);
    finalize_div<<<1, 256>>>(out + OFF_DIV);
    // 9. sf = attn @ vals^T  (64x128 tiles, 160 blocks, occ 2)
    sf_hmma_kernel<<<dim3(2, 5, BB), 256, SF_SMEM>>>(attn_t, vals, sfb, out + OFF_SF);
    // 10. heads layer 1 (bb1 + ch1 batched in z)
    hmma_nt_g<128, 2><<<dim3(2, 38, 2), 256, HS128>>>(sfb, hw1, h1,
        BB * NN, 256, 256, 256, 256, BB * NN, 0, 65536, (long long)BB * NN * 256,
        nullptr, bb1_b, ch1_b);
    // 11. LN+ReLU both heads
    ln_relu2_kernel<<<dim3(BB * NN, 2), 256>>>(h1, bbln_g, bbln_b, chln_g, chln_b);
    // 12. heads layer 2 (bb2 + ch2 batched)
    hmma_nt_g<128, 3><<<dim3(1, 38, 2), 256, HS128>>>(h1, hw2, h2,
        BB * NN, 256, 256, 256, 128, BB * NN, (long long)BB * NN * 256, 32768,
        (long long)BB * NN * 128, nullptr, bb2_b, ch2_b);
    // 13. finals
    gemm_nt<0><<<dim3(1, 38, 1), 256>>>(h2, bb3_w, out + OFF_BOXES, BB * NN, 4, 128, bb3_b);
    gemm_nt<2><<<dim3(1, 38, 1), 256>>>(h2 + (long long)BB * NN * 128, ch3_w, out + OFF_SCORES,
                                        BB * NN, 1, 128, ch3_b);
    gemm_nt<0><<<dim3(1, 38, 1), 256>>>(sfb, ctp_w, out + OFF_CLS, BB * NN, NCC, 256, ctp_b);
}

// round 9
// speedup vs baseline: 2.0273x; 1.0907x over previous
#include <cuda_runtime.h>
#include <cuda_bf16.h>
#include <cstdint>
#include <math.h>

// ---------------- problem constants ----------------
#define BB   16
#define CC   256
#define MM   4096          // H*W
#define HID  256
#define NN   300
#define NCC  80

// output layout (flattened tuple: boxes, scores, cls, maps, div, sf)
#define OFF_BOXES  0LL
#define OFF_SCORES 19200LL
#define OFF_CLS    24000LL
#define OFF_MAPS   408000LL
#define OFF_DIV    20068800LL
#define OFF_SF     20068801LL

// ---------------- device scratch ----------------
__device__ float g_ft   [BB * 128 * MM];            // feats transposed [b][m][128], tf32
__device__ float g_kt   [BB * 64 * MM];             // keys transposed [b][m][64], tf32
__device__ float g_vals [BB * 256 * MM];            // vals [b][c][m], tf32
__device__ __nv_bfloat16 g_logits[(long long)BB * 4 * NN * MM]; // bf16 logits scratch
__device__ float g_invn [BB * NN];
__device__ float g_sf   [BB * NN * HID];            // tf32-rounded sf for heads
__device__ float g_h1   [2 * BB * NN * 256];        // [bb, ch]
__device__ float g_h2   [2 * BB * NN * 128];
__device__ float g_bns  [128];
__device__ float g_bnt  [128];
__device__ float g_divpart[256];
__device__ float g_fpwt [128 * 256];                // tf32 weight copies
__device__ float g_keywt[64 * 256];
__device__ float g_valwt[256 * 256];
__device__ float g_qt   [NN * 64];
__device__ float g_hw1  [2 * 256 * 256];            // [bb1, ch1] rounded
__device__ float g_hw2  [2 * 128 * 256];            // [bb2, ch2] rounded
__device__ float g_pra  [320];                      // pos rank-2: Ay (64 key + 256 val)
__device__ float g_prb  [320];                      // Ax
__device__ float g_prc  [320];                      // C (incl. bias)

__device__ __forceinline__ float tf32_rna(float v) {
    uint32_t u;
    asm("cvt.rna.tf32.f32 %0, %1;" : "=r"(u) : "f"(v));
    return __uint_as_float(u);
}
__device__ __forceinline__ void mma_tf32(float c[4], const uint32_t a[4], const uint32_t b[2]) {
    asm volatile(
        "mma.sync.aligned.m16n8k8.row.col.f32.tf32.tf32.f32 "
        "{%0,%1,%2,%3}, {%4,%5,%6,%7}, {%8,%9}, {%0,%1,%2,%3};"
        : "+f"(c[0]), "+f"(c[1]), "+f"(c[2]), "+f"(c[3])
        : "r"(a[0]), "r"(a[1]), "r"(a[2]), "r"(a[3]), "r"(b[0]), "r"(b[1]));
}
__device__ __forceinline__ float grid_y(int m) { return -1.0f + (2.0f / 63.0f) * (float)(m >> 6); }
__device__ __forceinline__ float grid_x(int m) { return -1.0f + (2.0f / 63.0f) * (float)(m & 63); }

// ---------------- small kernels ----------------
__global__ void init_kernel(const float* __restrict__ fp_b, const float* __restrict__ bn_g,
                            const float* __restrict__ bn_b, const float* __restrict__ bn_m,
                            const float* __restrict__ bn_v) {
    int t = threadIdx.x;
    if (t < 128) {
        float s = bn_g[t] * rsqrtf(bn_v[t] + 1e-5f);
        g_bns[t] = s;
        g_bnt[t] = (fp_b[t] - bn_m[t]) * s + bn_b[t];
    }
}

struct RoundJob { const float* s; float* d; int n; float sc; };
struct RoundJobs { RoundJob j[8]; };
__global__ void round_many(RoundJobs jobs) {
    int tid = blockIdx.x * 256 + threadIdx.x;
    int stride = gridDim.x * 256;
#pragma unroll
    for (int k = 0; k < 8; k++) {
        const RoundJob J = jobs.j[k];
        for (int i = tid; i < J.n; i += stride) J.d[i] = tf32_rna(J.s[i] * J.sc);
    }
}

// pos rank-2 reduce: Ay/Ax/C per output channel (64 key + 256 val)
__global__ void pos_reduce_kernel(const float* __restrict__ key_w, const float* __restrict__ val_w,
                                  const float* __restrict__ pos_w, const float* __restrict__ pos_b,
                                  const float* __restrict__ key_b, const float* __restrict__ val_b)
{
    int idx = blockIdx.x * 256 + threadIdx.x;   // 0..959
    if (idx >= 960) return;
    int which = idx % 3;
    int oa = idx / 3;
    const float* w;
    float bias;
    if (oa < 64) { w = key_w + oa * 256 + 128; bias = key_b[oa]; }
    else         { w = val_w + (oa - 64) * 256 + 128; bias = val_b[oa - 64]; }
    float s = 0.f;
    for (int c = 0; c < 128; c++) {
        float p = (which == 0) ? pos_w[2 * c] : (which == 1) ? pos_w[2 * c + 1] : pos_b[c];
        s += w[c] * p;
    }
    if (which == 0) g_pra[oa] = s;
    else if (which == 1) g_prb[oa] = s;
    else g_prc[oa] = s + bias;
}

// ================= ft HMMA with fused transpose =================
#define FT_SMEM ((2 * 32 * 136 + 2 * 128 * 36) * 4)   // 71680 B

__global__ void __launch_bounds__(256, 1) ft_hmma(
    const float* __restrict__ xg, const float* __restrict__ Bw, float* __restrict__ Cb,
    const float* __restrict__ e1, const float* __restrict__ e2)
{
    extern __shared__ float smf[];
    float* As = smf;                    // [2][32][136]
    float* Bs = smf + 2 * 32 * 136;     // [2][128*36]
    int t = threadIdx.x, lane = t & 31, w = t >> 5;
    int wn0 = (w & 3) * 32, wc0 = (w >> 2) * 64;
    int g = lane >> 2, tq = lane & 3;
    int i0 = blockIdx.y * 128, b = blockIdx.z;
    const float* A = xg + (long long)b * CC * MM;
    float* C = Cb + (long long)b * MM * 128;
    int col4 = (t & 7) * 4, row0 = t >> 3;
    int am4 = (t & 31) * 4, ac0 = t >> 5;

    float acc[2][8][4];
#pragma unroll
    for (int mi = 0; mi < 2; mi++)
#pragma unroll
        for (int ni = 0; ni < 8; ni++)
#pragma unroll
            for (int r = 0; r < 4; r++) acc[mi][ni][r] = 0.f;

    float4 ra[4], rb[4];
#pragma unroll
    for (int i = 0; i < 4; i++) {
        int c = ac0 + 8 * i;
        ra[i] = *(const float4*)(A + (long long)c * MM + i0 + am4);
        rb[i] = *(const float4*)(Bw + (long long)(row0 + 32 * i) * 256 + col4);
    }
#pragma unroll
    for (int i = 0; i < 4; i++) {
        int c = ac0 + 8 * i;
        float4 v = ra[i];
        v.x = tf32_rna(v.x); v.y = tf32_rna(v.y); v.z = tf32_rna(v.z); v.w = tf32_rna(v.w);
        *(float4*)&As[c * 136 + am4] = v;
        *(float4*)&Bs[(row0 + 32 * i) * 36 + col4] = rb[i];
    }
    __syncthreads();

    for (int ch = 0; ch < 8; ch++) {
        int buf = ch & 1;
        bool more = (ch + 1) < 8;
        if (more) {
            int k0 = (ch + 1) * 32;
#pragma unroll
            for (int i = 0; i < 4; i++) {
                int c = k0 + ac0 + 8 * i;
                ra[i] = *(const float4*)(A + (long long)c * MM + i0 + am4);
                rb[i] = *(const float4*)(Bw + (long long)(row0 + 32 * i) * 256 + k0 + col4);
            }
        }
        const uint32_t* Asu = (const uint32_t*)(As + buf * 32 * 136);
        const uint32_t* Bsu = (const uint32_t*)(Bs + buf * 128 * 36);
#pragma unroll
        for (int ks = 0; ks < 4; ks++) {
            int kk = ks * 8 + tq;
            uint32_t a[2][4];
#pragma unroll
            for (int mi = 0; mi < 2; mi++) {
                int r = wn0 + 16 * mi + g;
                a[mi][0] = Asu[kk * 136 + r];
                a[mi][1] = Asu[kk * 136 + r + 8];
                a[mi][2] = Asu[(kk + 4) * 136 + r];
                a[mi][3] = Asu[(kk + 4) * 136 + r + 8];
            }
            uint32_t bf[8][2];
#pragma unroll
            for (int ni = 0; ni < 8; ni++) {
                int c = wc0 + ni * 8 + g;
                bf[ni][0] = Bsu[c * 36 + kk];
                bf[ni][1] = Bsu[c * 36 + kk + 4];
            }
#pragma unroll
            for (int mi = 0; mi < 2; mi++)
#pragma unroll
                for (int ni = 0; ni < 8; ni++)
                    mma_tf32(acc[mi][ni], a[mi], bf[ni]);
        }
        if (more) {
            float* Ad = As + (buf ^ 1) * 32 * 136;
            float* Bd = Bs + (buf ^ 1) * 128 * 36;
#pragma unroll
            for (int i = 0; i < 4; i++) {
                int c = ac0 + 8 * i;
                float4 v = ra[i];
                v.x = tf32_rna(v.x); v.y = tf32_rna(v.y); v.z = tf32_rna(v.z); v.w = tf32_rna(v.w);
                *(float4*)&Ad[c * 136 + am4] = v;
                *(float4*)&Bd[(row0 + 32 * i) * 36 + col4] = rb[i];
            }
        }
        __syncthreads();
    }

#pragma unroll
    for (int mi = 0; mi < 2; mi++) {
#pragma unroll
        for (int ni = 0; ni < 8; ni++) {
            int jg = wc0 + ni * 8 + 2 * tq;
#pragma unroll
            for (int hh = 0; hh < 2; hh++) {
                int i = i0 + wn0 + 16 * mi + g + 8 * hh;
                float v0 = tf32_rna(fmaxf(acc[mi][ni][2 * hh] * e1[jg] + e2[jg], 0.f));
                float v1 = tf32_rna(fmaxf(acc[mi][ni][2 * hh + 1] * e1[jg + 1] + e2[jg + 1], 0.f));
                *(float2*)(C + (long long)i * 128 + jg) = make_float2(v0, v1);
            }
        }
    }
}

// ================= generic NT HMMA tf32 =================
// EPI 2: acc+bias[j]        EPI 3: relu(acc+bias[j])   (bias z-selected via e1z)
// EPI 4: tf32(acc + pos_val(i=channel, j=m))   — vals epilogue
// EPI 5: tf32(acc + pos_key(i=m, j=o))         — kt epilogue
#define HS128 73728
#define HS64  55296

template<int NJ, int EPI>
__global__ void __launch_bounds__(256, 1) hmma_nt_g(
    const float* __restrict__ Ab, const float* __restrict__ Bb, float* __restrict__ Cb,
    int I, int K, int lda, int ldb, int ldc, int clampI,
    long long az, long long bz, long long cz,
    const float* __restrict__ e1, const float* __restrict__ e1z)
{
    extern __shared__ float smf[];
    const int NI_ACC = NJ / 16;
    const int NB = NJ / 32;
    float* As = smf;
    float* Bs = smf + 2 * 128 * 36;
    int t = threadIdx.x, lane = t & 31, w = t >> 5;
    int wn0 = (w & 3) * 32, wc0 = (w >> 2) * (NJ / 2);
    int g = lane >> 2, tq = lane & 3;
    int j0 = blockIdx.x * NJ, i0 = blockIdx.y * 128, b = blockIdx.z;
    const float* A = Ab + az * b;
    const float* B = Bb + bz * b;
    float* C = Cb + cz * b;
    int col4 = (t & 7) * 4, row0 = t >> 3;

    float acc[2][NI_ACC][4];
#pragma unroll
    for (int mi = 0; mi < 2; mi++)
#pragma unroll
        for (int ni = 0; ni < NI_ACC; ni++)
#pragma unroll
            for (int r = 0; r < 4; r++) acc[mi][ni][r] = 0.f;

    float4 ra[4], rb[NB];
#pragma unroll
    for (int i = 0; i < 4; i++) {
        int r = row0 + 32 * i;
        int ar = i0 + r; ar = ar < clampI ? ar : clampI - 1;
        ra[i] = *(const float4*)(A + (long long)ar * lda + col4);
    }
#pragma unroll
    for (int i = 0; i < NB; i++) {
        int r = row0 + 32 * i;
        rb[i] = *(const float4*)(B + (long long)(j0 + r) * ldb + col4);
    }
#pragma unroll
    for (int i = 0; i < 4; i++) { int r = row0 + 32 * i; *(float4*)&As[r * 36 + col4] = ra[i]; }
#pragma unroll
    for (int i = 0; i < NB; i++) { int r = row0 + 32 * i; *(float4*)&Bs[r * 36 + col4] = rb[i]; }
    __syncthreads();

    int nch = K / 32;
    for (int ch = 0; ch < nch; ch++) {
        int buf = ch & 1;
        bool more = (ch + 1) < nch;
        if (more) {
            int k0 = (ch + 1) * 32 + col4;
#pragma unroll
            for (int i = 0; i < 4; i++) {
                int r = row0 + 32 * i;
                int ar = i0 + r; ar = ar < clampI ? ar : clampI - 1;
                ra[i] = *(const float4*)(A + (long long)ar * lda + k0);
            }
#pragma unroll
            for (int i = 0; i < NB; i++) {
                int r = row0 + 32 * i;
                rb[i] = *(const float4*)(B + (long long)(j0 + r) * ldb + k0);
            }
        }
        const uint32_t* Asu = (const uint32_t*)(As + buf * 128 * 36);
        const uint32_t* Bsu = (const uint32_t*)(Bs + buf * NJ * 36);
#pragma unroll
        for (int ks = 0; ks < 4; ks++) {
            int kk = ks * 8 + tq;
            uint32_t a[2][4];
#pragma unroll
            for (int mi = 0; mi < 2; mi++) {
                int r = wn0 + 16 * mi + g;
                a[mi][0] = Asu[r * 36 + kk];
                a[mi][1] = Asu[(r + 8) * 36 + kk];
                a[mi][2] = Asu[r * 36 + kk + 4];
                a[mi][3] = Asu[(r + 8) * 36 + kk + 4];
            }
            uint32_t bf[NI_ACC][2];
#pragma unroll
            for (int ni = 0; ni < NI_ACC; ni++) {
                int c = wc0 + ni * 8 + g;
                bf[ni][0] = Bsu[c * 36 + kk];
                bf[ni][1] = Bsu[c * 36 + kk + 4];
            }
#pragma unroll
            for (int mi = 0; mi < 2; mi++)
#pragma unroll
                for (int ni = 0; ni < NI_ACC; ni++)
                    mma_tf32(acc[mi][ni], a[mi], bf[ni]);
        }
        if (more) {
            float* Ad = As + (buf ^ 1) * 128 * 36;
            float* Bd = Bs + (buf ^ 1) * NJ * 36;
#pragma unroll
            for (int i = 0; i < 4; i++) { int r = row0 + 32 * i; *(float4*)&Ad[r * 36 + col4] = ra[i]; }
#pragma unroll
            for (int i = 0; i < NB; i++) { int r = row0 + 32 * i; *(float4*)&Bd[r * 36 + col4] = rb[i]; }
        }
        __syncthreads();
    }

    const float* bp = (EPI == 2 || EPI == 3) ? ((b != 0 && e1z != nullptr) ? e1z : e1) : nullptr;
#pragma unroll
    for (int mi = 0; mi < 2; mi++) {
#pragma unroll
        for (int ni = 0; ni < NI_ACC; ni++) {
            int jg = j0 + wc0 + ni * 8 + 2 * tq;
#pragma unroll
            for (int hh = 0; hh < 2; hh++) {
                int i = i0 + wn0 + 16 * mi + g + 8 * hh;
                if (i >= I) continue;
                float v0 = acc[mi][ni][2 * hh], v1 = acc[mi][ni][2 * hh + 1];
                if (EPI == 2) {
                    v0 = v0 + bp[jg]; v1 = v1 + bp[jg + 1];
                } else if (EPI == 3) {
                    v0 = fmaxf(v0 + bp[jg], 0.f); v1 = fmaxf(v1 + bp[jg + 1], 0.f);
                } else if (EPI == 4) {
                    // i = val channel, jg = m
                    float ay = g_pra[64 + i], ax = g_prb[64 + i], cc = g_prc[64 + i];
                    v0 = tf32_rna(v0 + ay * grid_y(jg) + ax * grid_x(jg) + cc);
                    v1 = tf32_rna(v1 + ay * grid_y(jg + 1) + ax * grid_x(jg + 1) + cc);
                } else if (EPI == 5) {
                    // i = m, jg = key channel
                    float yi = grid_y(i), xi = grid_x(i);
                    v0 = tf32_rna(v0 + g_pra[jg] * yi + g_prb[jg] * xi + g_prc[jg]);
                    v1 = tf32_rna(v1 + g_pra[jg + 1] * yi + g_prb[jg + 1] * xi + g_prc[jg + 1]);
                }
                *(float2*)(C + (long long)i * ldc + jg) = make_float2(v0, v1);
            }
        }
    }
}

// ================= logits HMMA (K=16), bf16 output =================
__global__ void __launch_bounds__(256) logits_hmma(
    const float* __restrict__ qt, const float* __restrict__ kt,
    __nv_bfloat16* __restrict__ logits)
{
    __shared__ float As[128 * 20], Bs[128 * 20];
    int t = threadIdx.x, lane = t & 31, w = t >> 5;
    int wn0 = (w & 3) * 32, wc0 = (w >> 2) * 64;
    int g = lane >> 2, tq = lane & 3;
    int m0 = blockIdx.x * 128, n0 = blockIdx.y * 128;
    int z = blockIdx.z, b = z >> 2, h = z & 3;
    const float* Aq = qt + h * 16;
    const float* Bk = kt + (long long)b * MM * 64 + h * 16;
#pragma unroll
    for (int i = 0; i < 2; i++) {
        int gi = t + i * 256;
        int row = gi >> 2, gc = (gi & 3) * 4;
        int nr = n0 + row; nr = nr < NN ? nr : NN - 1;
        *(float4*)&As[row * 20 + gc] = *(const float4*)(Aq + (long long)nr * 64 + gc);
        *(float4*)&Bs[row * 20 + gc] = *(const float4*)(Bk + (long long)(m0 + row) * 64 + gc);
    }
    __syncthreads();
    float acc[2][8][4];
#pragma unroll
    for (int mi = 0; mi < 2; mi++)
#pragma unroll
        for (int ni = 0; ni < 8; ni++)
#pragma unroll
            for (int r = 0; r < 4; r++) acc[mi][ni][r] = 0.f;
    const uint32_t* Asu = (const uint32_t*)As;
    const uint32_t* Bsu = (const uint32_t*)Bs;
#pragma unroll
    for (int ks = 0; ks < 2; ks++) {
        int kk = ks * 8 + tq;
        uint32_t a[2][4];
#pragma unroll
        for (int mi = 0; mi < 2; mi++) {
            int r = wn0 + 16 * mi + g;
            a[mi][0] = Asu[r * 20 + kk];
            a[mi][1] = Asu[(r + 8) * 20 + kk];
            a[mi][2] = Asu[r * 20 + kk + 4];
            a[mi][3] = Asu[(r + 8) * 20 + kk + 4];
        }
        uint32_t bf[8][2];
#pragma unroll
        for (int ni = 0; ni < 8; ni++) {
            int c = wc0 + ni * 8 + g;
            bf[ni][0] = Bsu[c * 20 + kk];
            bf[ni][1] = Bsu[c * 20 + kk + 4];
        }
#pragma unroll
        for (int mi = 0; mi < 2; mi++)
#pragma unroll
            for (int ni = 0; ni < 8; ni++)
                mma_tf32(acc[mi][ni], a[mi], bf[ni]);
    }
    long long base = (long long)z * NN * MM;
#pragma unroll
    for (int mi = 0; mi < 2; mi++) {
#pragma unroll
        for (int ni = 0; ni < 8; ni++) {
            int m = m0 + wc0 + ni * 8 + 2 * tq;
#pragma unroll
            for (int hh = 0; hh < 2; hh++) {
                int n = n0 + wn0 + 16 * mi + g + 8 * hh;
                if (n < NN) {
                    __nv_bfloat162 bv = __floats2bfloat162_rn(
                        acc[mi][ni][2 * hh], acc[mi][ni][2 * hh + 1]);
                    *(__nv_bfloat162*)(logits + base + (long long)n * MM + m) = bv;
                }
            }
        }
    }
}

// ---------------- register-resident softmax (bf16 in, fp32 maps out) ----------------
__global__ void __launch_bounds__(256) softmax_kernel(
    const __nv_bfloat16* __restrict__ logits,
    float* __restrict__ attn, float* __restrict__ invn)
{
    __shared__ float red[40];
    int bn = blockIdx.x;
    int b = bn / NN, n = bn - b * NN;
    int t = threadIdx.x, lane = t & 31, wid = t >> 5;
    float v[4][16];
#pragma unroll
    for (int h = 0; h < 4; h++) {
        const __nv_bfloat162* src = (const __nv_bfloat162*)
            (logits + ((long long)(b * 4 + h) * NN + n) * MM);
#pragma unroll
        for (int kk = 0; kk < 8; kk++) {
            __nv_bfloat162 e = src[t + 256 * kk];
            v[h][2 * kk]     = __bfloat162float(e.x);
            v[h][2 * kk + 1] = __bfloat162float(e.y);
        }
    }
    float lm[4];
#pragma unroll
    for (int h = 0; h < 4; h++) {
        float m = v[h][0];
#pragma unroll
        for (int k = 1; k < 16; k++) m = fmaxf(m, v[h][k]);
#pragma unroll
        for (int s = 16; s > 0; s >>= 1) m = fmaxf(m, __shfl_xor_sync(0xFFFFFFFFu, m, s));
        lm[h] = m;
    }
    if (lane == 0) {
#pragma unroll
        for (int h = 0; h < 4; h++) red[wid * 4 + h] = lm[h];
    }
    __syncthreads();
    if (t < 32) {
        float x = red[t];
        x = fmaxf(x, __shfl_xor_sync(0xFFFFFFFFu, x, 4));
        x = fmaxf(x, __shfl_xor_sync(0xFFFFFFFFu, x, 8));
        x = fmaxf(x, __shfl_xor_sync(0xFFFFFFFFu, x, 16));
        if (t < 4) red[32 + t] = x;
    }
    __syncthreads();
    float mx[4];
#pragma unroll
    for (int h = 0; h < 4; h++) mx[h] = red[32 + h];
    float ls[4];
#pragma unroll
    for (int h = 0; h < 4; h++) {
        float s = 0.f;
#pragma unroll
        for (int k = 0; k < 16; k++) {
            float e = __expf(v[h][k] - mx[h]);
            v[h][k] = e; s += e;
        }
#pragma unroll
        for (int st = 16; st > 0; st >>= 1) s += __shfl_xor_sync(0xFFFFFFFFu, s, st);
        ls[h] = s;
    }
    __syncthreads();
    if (lane == 0) {
#pragma unroll
        for (int h = 0; h < 4; h++) red[wid * 4 + h] = ls[h];
    }
    __syncthreads();
    if (t < 32) {
        float x = red[t];
        x += __shfl_xor_sync(0xFFFFFFFFu, x, 4);
        x += __shfl_xor_sync(0xFFFFFFFFu, x, 8);
        x += __shfl_xor_sync(0xFFFFFFFFu, x, 16);
        if (t < 4) red[36 + t] = 0.25f / x;
    }
    __syncthreads();
    float rs[4];
#pragma unroll
    for (int h = 0; h < 4; h++) rs[h] = red[36 + h];
    float ss = 0.f;
    float2* dst2 = (float2*)(attn + (long long)bn * MM);
#pragma unroll
    for (int kk = 0; kk < 8; kk++) {
        float a0 = v[0][2 * kk] * rs[0] + v[1][2 * kk] * rs[1]
                 + v[2][2 * kk] * rs[2] + v[3][2 * kk] * rs[3];
        float a1 = v[0][2 * kk + 1] * rs[0] + v[1][2 * kk + 1] * rs[1]
                 + v[2][2 * kk + 1] * rs[2] + v[3][2 * kk + 1] * rs[3];
        dst2[t + 256 * kk] = make_float2(a0, a1);
        ss += a0 * a0 + a1 * a1;
    }
#pragma unroll
    for (int st = 16; st > 0; st >>= 1) ss += __shfl_xor_sync(0xFFFFFFFFu, ss, st);
    __syncthreads();
    if (lane == 0) red[wid] = ss;
    __syncthreads();
    if (t == 0) {
        float s = 0.f;
#pragma unroll
        for (int i = 0; i < 8; i++) s += red[i];
        invn[bn] = 1.0f / fmaxf(sqrtf(s), 1e-12f);
    }
}

// ---------------- diversity ----------------
__global__ void div_s_kernel(const float* __restrict__ attn, const float* __restrict__ invn)
{
    __shared__ float sinv[304];
    __shared__ float red[256];
    int b = blockIdx.y, t = threadIdx.x;
    for (int i = t; i < NN; i += 256) sinv[i] = invn[b * NN + i];
    __syncthreads();
    int m = blockIdx.x * 256 + t;
    const float* base = attn + (long long)b * NN * MM + m;
    float s = 0.f;
    for (int n = 0; n < NN; n++) s += base[(long long)n * MM] * sinv[n];
    red[t] = s * s; __syncthreads();
    for (int k = 128; k > 0; k >>= 1) { if (t < k) red[t] += red[t + k]; __syncthreads(); }
    if (t == 0) g_divpart[b * 16 + blockIdx.x] = red[0];
}

__global__ void finalize_div(float* __restrict__ outdiv)
{
    __shared__ float red[256];
    int t = threadIdx.x;
    red[t] = g_divpart[t]; __syncthreads();
    for (int k = 128; k > 0; k >>= 1) { if (t < k) red[t] += red[t + k]; __syncthreads(); }
    if (t == 0) outdiv[0] = (red[0] - (float)(BB * NN)) * (0.1f / ((float)NN * (NN - 1)));
}

// ---------------- batched LayerNorm(256) + ReLU (tf32 out) ----------------
__global__ void __launch_bounds__(256) ln_relu2_kernel(
    float* __restrict__ zb,
    const float* __restrict__ g0, const float* __restrict__ b0,
    const float* __restrict__ g1, const float* __restrict__ b1)
{
    __shared__ float red[8];
    __shared__ float bc;
    int row = blockIdx.x, sel = blockIdx.y;
    int t = threadIdx.x, lane = t & 31, wid = t >> 5;
    float* z = zb + (long long)sel * BB * NN * 256;
    const float* g = sel ? g1 : g0;
    const float* bb = sel ? b1 : b0;
    float v = z[(long long)row * 256 + t];
    float s = v;
#pragma unroll
    for (int st = 16; st > 0; st >>= 1) s += __shfl_xor_sync(0xFFFFFFFFu, s, st);
    if (lane == 0) red[wid] = s;
    __syncthreads();
    if (t == 0) { float a = 0.f; for (int i = 0; i < 8; i++) a += red[i]; bc = a * (1.f / 256.f); }
    __syncthreads();
    float mu = bc;
    float d = v - mu;
    s = d * d;
#pragma unroll
    for (int st = 16; st > 0; st >>= 1) s += __shfl_xor_sync(0xFFFFFFFFu, s, st);
    __syncthreads();
    if (lane == 0) red[wid] = s;
    __syncthreads();
    if (t == 0) { float a = 0.f; for (int i = 0; i < 8; i++) a += red[i]; bc = a * (1.f / 256.f); }
    __syncthreads();
    float var = bc;
    float o = d * rsqrtf(var + 1e-5f) * g[t] + bb[t];
    z[(long long)row * 256 + t] = tf32_rna(fmaxf(o, 0.f));
}

// ---------------- SIMT GEMM NT (small finals) ----------------
#define TILE 128
#define BK   16

template<int EPI>
__global__ void __launch_bounds__(256) gemm_nt(
    const float* __restrict__ Ab, const float* __restrict__ Bb, float* __restrict__ Cb,
    int I, int J, int K, const float* __restrict__ bias)
{
    __shared__ float As[BK][TILE + 4];
    __shared__ float Bs[BK][TILE + 4];
    int t = threadIdx.x, tx = t & 15, ty = t >> 4;
    int iB = blockIdx.y * TILE, jB = blockIdx.x * TILE;

    float acc[8][8];
#pragma unroll
    for (int i = 0; i < 8; i++)
#pragma unroll
        for (int j = 0; j < 8; j++) acc[i][j] = 0.f;

    for (int k0 = 0; k0 < K; k0 += BK) {
#pragma unroll
        for (int r = 0; r < 2; r++) {
            int idx = t + r * 256;
            int row = idx >> 2, kq = (idx & 3) * 4;
            float4 v = make_float4(0.f, 0.f, 0.f, 0.f);
            int i = iB + row;
            if (i < I) v = *(const float4*)(Ab + (long long)i * K + k0 + kq);
            As[kq + 0][row] = v.x; As[kq + 1][row] = v.y;
            As[kq + 2][row] = v.z; As[kq + 3][row] = v.w;
        }
#pragma unroll
        for (int r = 0; r < 2; r++) {
            int idx = t + r * 256;
            int row = idx >> 2, kq = (idx & 3) * 4;
            float4 v = make_float4(0.f, 0.f, 0.f, 0.f);
            int j = jB + row;
            if (j < J) v = *(const float4*)(Bb + (long long)j * K + k0 + kq);
            Bs[kq + 0][row] = v.x; Bs[kq + 1][row] = v.y;
            Bs[kq + 2][row] = v.z; Bs[kq + 3][row] = v.w;
        }
        __syncthreads();
#pragma unroll
        for (int k = 0; k < BK; k++) {
            float a[8], bv[8];
            *(float4*)&a[0]  = *(const float4*)&As[k][ty * 4];
            *(float4*)&a[4]  = *(const float4*)&As[k][ty * 4 + 64];
            *(float4*)&bv[0] = *(const float4*)&Bs[k][tx * 4];
            *(float4*)&bv[4] = *(const float4*)&Bs[k][tx * 4 + 64];
#pragma unroll
            for (int i = 0; i < 8; i++)
#pragma unroll
                for (int j = 0; j < 8; j++) acc[i][j] += a[i] * bv[j];
        }
        __syncthreads();
    }
#pragma unroll
    for (int i = 0; i < 8; i++) {
        int ii = iB + (i < 4 ? ty * 4 + i : 64 + ty * 4 + i - 4);
        if (ii >= I) continue;
#pragma unroll
        for (int j = 0; j < 8; j++) {
            int jj = jB + (j < 4 ? tx * 4 + j : 64 + tx * 4 + j - 4);
            if (jj >= J) continue;
            float v = acc[i][j];
            if (bias) v += bias[jj];
            if (EPI == 1) v = fmaxf(v, 0.f);
            else if (EPI == 2) v = 1.0f / (1.0f + __expf(-v));
            Cb[(long long)ii * J + jj] = v;
        }
    }
}

// ================= sf = attn @ vals^T — 64n x 128c tiles, occ 2, tf32-round in copy =================
#define SF_SMEM ((2 * 64 * 36 + 2 * 128 * 36) * 4)   // 55296

__global__ void __launch_bounds__(256, 2) sf_hmma_kernel(
    const float* __restrict__ attn, const float* __restrict__ vals,
    float* __restrict__ sfb, float* __restrict__ outsf)
{
    extern __shared__ float smf[];
    float* As = smf;                    // [2][64*36]
    float* Bs = smf + 2 * 64 * 36;      // [2][128*36]
    int t = threadIdx.x;
    int lane = t & 31, w = t >> 5;
    int wn0 = (w & 1) * 32, wc0 = (w >> 1) * 32;
    int g = lane >> 2, tq = lane & 3;
    int n0 = blockIdx.y * 64, c0 = blockIdx.x * 128, b = blockIdx.z;

    int col4 = (t & 7) * 4;
    int row0 = t >> 3;                  // 0..31

    const float* Ab = attn + (long long)b * NN * MM;
    const float* Bb = vals + (long long)b * HID * MM;

    float acc[2][4][4];
#pragma unroll
    for (int mi = 0; mi < 2; mi++)
#pragma unroll
        for (int ni = 0; ni < 4; ni++)
#pragma unroll
            for (int r = 0; r < 4; r++) acc[mi][ni][r] = 0.f;

    float4 ra[2], rb[4];
#pragma unroll
    for (int i = 0; i < 2; i++) {
        int r = row0 + 32 * i;
        int an = n0 + r; if (an > NN - 1) an = NN - 1;
        ra[i] = *(const float4*)(Ab + (long long)an * MM + col4);
    }
#pragma unroll
    for (int i = 0; i < 4; i++) {
        int r = row0 + 32 * i;
        rb[i] = *(const float4*)(Bb + (long long)(c0 + r) * MM + col4);
    }
#pragma unroll
    for (int i = 0; i < 2; i++) {
        int r = row0 + 32 * i;
        float4 v = ra[i];
        v.x = tf32_rna(v.x); v.y = tf32_rna(v.y); v.z = tf32_rna(v.z); v.w = tf32_rna(v.w);
        *(float4*)&As[r * 36 + col4] = v;
    }
#pragma unroll
    for (int i = 0; i < 4; i++) { int r = row0 + 32 * i; *(float4*)&Bs[r * 36 + col4] = rb[i]; }
    __syncthreads();

    for (int ch = 0; ch < MM / 32; ch++) {
        int buf = ch & 1;
        bool more = (ch + 1) < MM / 32;
        if (more) {
            int k0 = (ch + 1) * 32 + col4;
#pragma unroll
            for (int i = 0; i < 2; i++) {
                int r = row0 + 32 * i;
                int an = n0 + r; if (an > NN - 1) an = NN - 1;
                ra[i] = *(const float4*)(Ab + (long long)an * MM + k0);
            }
#pragma unroll
            for (int i = 0; i < 4; i++) {
                int r = row0 + 32 * i;
                rb[i] = *(const float4*)(Bb + (long long)(c0 + r) * MM + k0);
            }
        }
        const uint32_t* Asu = (const uint32_t*)(As + buf * 64 * 36);
        const uint32_t* Bsu = (const uint32_t*)(Bs + buf * 128 * 36);
#pragma unroll
        for (int ks = 0; ks < 4; ks++) {
            int kk = ks * 8 + tq;
            uint32_t a[2][4];
#pragma unroll
            for (int mi = 0; mi < 2; mi++) {
                int r = wn0 + 16 * mi + g;
                a[mi][0] = Asu[r * 36 + kk];
                a[mi][1] = Asu[(r + 8) * 36 + kk];
                a[mi][2] = Asu[r * 36 + kk + 4];
                a[mi][3] = Asu[(r + 8) * 36 + kk + 4];
            }
            uint32_t bf[4][2];
#pragma unroll
            for (int ni = 0; ni < 4; ni++) {
                int c = wc0 + ni * 8 + g;
                bf[ni][0] = Bsu[c * 36 + kk];
                bf[ni][1] = Bsu[c * 36 + kk + 4];
            }
#pragma unroll
            for (int mi = 0; mi < 2; mi++)
#pragma unroll
                for (int ni = 0; ni < 4; ni++)
                    mma_tf32(acc[mi][ni], a[mi], bf[ni]);
        }
        if (more) {
            float* Ad = As + (buf ^ 1) * 64 * 36;
            float* Bd = Bs + (buf ^ 1) * 128 * 36;
#pragma unroll
            for (int i = 0; i < 2; i++) {
                int r = row0 + 32 * i;
                float4 v = ra[i];
                v.x = tf32_rna(v.x); v.y = tf32_rna(v.y); v.z = tf32_rna(v.z); v.w = tf32_rna(v.w);
                *(float4*)&Ad[r * 36 + col4] = v;
            }
#pragma unroll
            for (int i = 0; i < 4; i++) { int r = row0 + 32 * i; *(float4*)&Bd[r * 36 + col4] = rb[i]; }
        }
        __syncthreads();
    }

#pragma unroll
    for (int mi = 0; mi < 2; mi++) {
#pragma unroll
        for (int ni = 0; ni < 4; ni++) {
            int c = c0 + wc0 + ni * 8 + 2 * tq;
#pragma unroll
            for (int hh = 0; hh < 2; hh++) {
                int n1 = n0 + wn0 + 16 * mi + g + 8 * hh;
                if (n1 < NN) {
                    long long o = ((long long)b * NN + n1) * HID + c;
                    float vx = acc[mi][ni][2 * hh], vy = acc[mi][ni][2 * hh + 1];
                    *(float2*)(sfb + o) = make_float2(tf32_rna(vx), tf32_rna(vy));
                    outsf[o] = vx; outsf[o + 1] = vy;
                }
            }
        }
    }
}

// ---------------- host ----------------
extern "C" void kernel_launch(void* const* d_in, const int* in_sizes, int n_in,
                              void* d_out_, int out_size)
{
    const float* x      = (const float*)d_in[0];
    const float* q      = (const float*)d_in[1];
    const float* pos_w  = (const float*)d_in[2];
    const float* pos_b  = (const float*)d_in[3];
    const float* fp_w   = (const float*)d_in[4];
    const float* fp_b   = (const float*)d_in[5];
    const float* bn_g   = (const float*)d_in[6];
    const float* bn_b   = (const float*)d_in[7];
    const float* bn_m   = (const float*)d_in[8];
    const float* bn_v   = (const float*)d_in[9];
    const float* key_w  = (const float*)d_in[10];
    const float* key_b  = (const float*)d_in[11];
    const float* val_w  = (const float*)d_in[12];
    const float* val_b  = (const float*)d_in[13];
    const float* ctp_w  = (const float*)d_in[14];
    const float* ctp_b  = (const float*)d_in[15];
    const float* bb1_w  = (const float*)d_in[16];
    const float* bb1_b  = (const float*)d_in[17];
    const float* bbln_g = (const float*)d_in[18];
    const float* bbln_b = (const float*)d_in[19];
    const float* bb2_w  = (const float*)d_in[20];
    const float* bb2_b  = (const float*)d_in[21];
    const float* bb3_w  = (const float*)d_in[22];
    const float* bb3_b  = (const float*)d_in[23];
    const float* ch1_w  = (const float*)d_in[24];
    const float* ch1_b  = (const float*)d_in[25];
    const float* chln_g = (const float*)d_in[26];
    const float* chln_b = (const float*)d_in[27];
    const float* ch2_w  = (const float*)d_in[28];
    const float* ch2_b  = (const float*)d_in[29];
    const float* ch3_w  = (const float*)d_in[30];
    const float* ch3_b  = (const float*)d_in[31];
    float* out = (float*)d_out_;

    float *ft, *kt, *vals, *invn, *sfb, *h1, *h2, *bns, *bnt,
          *fpwt, *keywt, *valwt, *qt, *hw1, *hw2;
    __nv_bfloat16* logits;
    cudaGetSymbolAddress((void**)&ft,     g_ft);
    cudaGetSymbolAddress((void**)&kt,     g_kt);
    cudaGetSymbolAddress((void**)&vals,   g_vals);
    cudaGetSymbolAddress((void**)&logits, g_logits);
    cudaGetSymbolAddress((void**)&invn,   g_invn);
    cudaGetSymbolAddress((void**)&sfb,    g_sf);
    cudaGetSymbolAddress((void**)&h1,     g_h1);
    cudaGetSymbolAddress((void**)&h2,     g_h2);
    cudaGetSymbolAddress((void**)&bns,    g_bns);
    cudaGetSymbolAddress((void**)&bnt,    g_bnt);
    cudaGetSymbolAddress((void**)&fpwt,   g_fpwt);
    cudaGetSymbolAddress((void**)&keywt,  g_keywt);
    cudaGetSymbolAddress((void**)&valwt,  g_valwt);
    cudaGetSymbolAddress((void**)&qt,     g_qt);
    cudaGetSymbolAddress((void**)&hw1,    g_hw1);
    cudaGetSymbolAddress((void**)&hw2,    g_hw2);

    cudaFuncSetAttribute(sf_hmma_kernel, cudaFuncAttributeMaxDynamicSharedMemorySize, SF_SMEM);
    cudaFuncSetAttribute(ft_hmma, cudaFuncAttributeMaxDynamicSharedMemorySize, FT_SMEM);
    cudaFuncSetAttribute(hmma_nt_g<128, 4>, cudaFuncAttributeMaxDynamicSharedMemorySize, HS128);
    cudaFuncSetAttribute(hmma_nt_g<64, 5>,  cudaFuncAttributeMaxDynamicSharedMemorySize, HS64);
    cudaFuncSetAttribute(hmma_nt_g<128, 2>, cudaFuncAttributeMaxDynamicSharedMemorySize, HS128);
    cudaFuncSetAttribute(hmma_nt_g<128, 3>, cudaFuncAttributeMaxDynamicSharedMemorySize, HS128);

    // 1. BN fold + all tf32 weight rounds in one launch
    init_kernel<<<1, 128>>>(fp_b, bn_g, bn_b, bn_m, bn_v);
    RoundJobs rj;
    rj.j[0] = {fp_w,  fpwt,        128 * 256, 1.f};
    rj.j[1] = {key_w, keywt,       64 * 256,  1.f};
    rj.j[2] = {val_w, valwt,       256 * 256, 1.f};
    rj.j[3] = {q,     qt,          NN * 64,   0.25f};
    rj.j[4] = {bb1_w, hw1,         256 * 256, 1.f};
    rj.j[5] = {ch1_w, hw1 + 65536, 256 * 256, 1.f};
    rj.j[6] = {bb2_w, hw2,         128 * 256, 1.f};
    rj.j[7] = {ch2_w, hw2 + 32768, 128 * 256, 1.f};
    round_many<<<160, 256>>>(rj);
    // 2. pos rank-2 reduce (eval now fused into GEMM epilogues)
    pos_reduce_kernel<<<4, 256>>>(key_w, val_w, pos_w, pos_b, key_b, val_b);
    // 3. ft = tf32(relu(bn(x^T @ fp_w^T))) — fused transpose
    ft_hmma<<<dim3(1, 32, BB), 256, FT_SMEM>>>(x, fpwt, ft, bns, bnt);
    // 4. kt = tf32(ft @ key_w^T + pos_key)  (pos inline, EPI 5)
    hmma_nt_g<64, 5><<<dim3(1, 32, BB), 256, HS64>>>(ft, keywt, kt,
        MM, 128, 128, 256, 64, MM, (long long)MM * 128, 0, (long long)MM * 64,
        nullptr, nullptr);
    // 5. vals = tf32(val_w @ ft^T + pos_val)  (pos inline, EPI 4)
    hmma_nt_g<128, 4><<<dim3(32, 2, BB), 256, HS128>>>(valwt, ft, vals,
        256, 128, 256, 128, MM, 256, 0, (long long)MM * 128, (long long)MM * 256,
        nullptr, nullptr);
    // 6. logits (bf16 out)
    logits_hmma<<<dim3(32, 3, BB * 4), 256>>>(qt, kt, logits);
    // 7. softmax (bf16 in, fp32 maps out)
    softmax_kernel<<<BB * NN, 256>>>(logits, out + OFF_MAPS, invn);
    // 8. diversity
    div_s_kernel<<<dim3(16, BB), 256>>>(out + OFF_MAPS, invn);
    finalize_div<<<1, 256>>>(out + OFF_DIV);
    // 9. sf = attn @ vals^T  (reads fp32 maps, rounds to tf32 in copy)
    sf_hmma_kernel<<<dim3(2, 5, BB), 256, SF_SMEM>>>(out + OFF_MAPS, vals, sfb, out + OFF_SF);
    // 10. heads layer 1 (bb1 + ch1 batched in z)
    hmma_nt_g<128, 2><<<dim3(2, 38, 2), 256, HS128>>>(sfb, hw1, h1,
        BB * NN, 256, 256, 256, 256, BB * NN, 0, 65536, (long long)BB * NN * 256,
        bb1_b, ch1_b);
    // 11. LN+ReLU both heads
    ln_relu2_kernel<<<dim3(BB * NN, 2), 256>>>(h1, bbln_g, bbln_b, chln_g, chln_b);
    // 12. heads layer 2 (bb2 + ch2 batched)
    hmma_nt_g<128, 3><<<dim3(1, 38, 2), 256, HS128>>>(h1, hw2, h2,
        BB * NN, 256, 256, 256, 128, BB * NN, (long long)BB * NN * 256, 32768,
        (long long)BB * NN * 128, bb2_b, ch2_b);
    // 13. finals
    gemm_nt<0><<<dim3(1, 38, 1), 256>>>(h2, bb3_w, out + OFF_BOXES, BB * NN, 4, 128, bb3_b);
    gemm_nt<2><<<dim3(1, 38, 1), 256>>>(h2 + (long long)BB * NN * 128, ch3_w, out + OFF_SCORES,
                                        BB * NN, 1, 128, ch3_b);
    gemm_nt<0><<<dim3(1, 38, 1), 256>>>(sfb, ctp_w, out + OFF_CLS, BB * NN, NCC, 256, ctp_b);
}